// round 1
// baseline (speedup 1.0000x reference)
#include <cuda_runtime.h>
#include <math.h>

// ---------------------------------------------------------------------------
// Problem constants
// ---------------------------------------------------------------------------
constexpr int Bb   = 2;
constexpr int Hh   = 256;
constexpr int Wdim = 256;
constexpr int Cc   = 96;
constexpr int HEADS= 6;
constexpr int HID  = 192;
constexpr int TOK  = Bb * Hh * Wdim;          // 131072 tokens

// ---------------------------------------------------------------------------
// Static device scratch (allocation-free rule: __device__ globals)
// ---------------------------------------------------------------------------
__device__ float g_lnx [TOK * Cc];
__device__ float g_lnr [TOK * Cc];
__device__ float g_qkvx[TOK * 288];
__device__ float g_qkvr[TOK * 288];
__device__ float g_y   [TOK * Cc];
__device__ float g_tmp [TOK * Cc];
__device__ float g_x2  [TOK * Cc];
__device__ float g_h1  [TOK * HID];
__device__ float g_h2  [TOK * HID];
__device__ float g_qkv_wT[96 * 288];
__device__ float g_proj_wT[96 * 96];
__device__ float g_fc1_wT[96 * 192];
__device__ float g_fc2_wT[192 * 96];

#define DEV __device__ __forceinline__

DEV float gelu_f(float v) { return 0.5f * v * (1.0f + erff(v * 0.70710678118654752f)); }

// ---------------------------------------------------------------------------
// Tiny transpose: dst[c*R + r] = src[r*C + c]
// ---------------------------------------------------------------------------
__global__ void transpose_k(const float* __restrict__ src, float* __restrict__ dst, int R, int C)
{
    int i = blockIdx.x * 256 + threadIdx.x;
    if (i < R * C) {
        int r = i / C, c = i % C;
        dst[c * R + r] = src[i];
    }
}

// ---------------------------------------------------------------------------
// LayerNorm over C=96, with optional (+shift,+shift) gather (implements roll)
// out[b,h,w,:] = LN(in[b,(h+shift)%256,(w+shift)%256,:]) * g + b
// one warp per token
// ---------------------------------------------------------------------------
__global__ void ln_kernel(const float* __restrict__ in, const float* __restrict__ g,
                          const float* __restrict__ bt, float* __restrict__ out, int shift)
{
    int gid  = blockIdx.x * blockDim.x + threadIdx.x;
    int tok  = gid >> 5;
    int lane = gid & 31;
    if (tok >= TOK) return;
    int b = tok >> 16, rr = tok & 65535, h = rr >> 8, w = rr & 255;
    const float* src = in + (size_t)((b << 16) | (((h + shift) & 255) << 8) | ((w + shift) & 255)) * 96;
    float v0 = src[lane], v1 = src[lane + 32], v2 = src[lane + 64];
    float s = v0 + v1 + v2;
    #pragma unroll
    for (int o = 16; o > 0; o >>= 1) s += __shfl_xor_sync(0xffffffffu, s, o);
    float mu = s * (1.0f / 96.0f);
    float d0 = v0 - mu, d1 = v1 - mu, d2 = v2 - mu;
    float sq = d0 * d0 + d1 * d1 + d2 * d2;
    #pragma unroll
    for (int o = 16; o > 0; o >>= 1) sq += __shfl_xor_sync(0xffffffffu, sq, o);
    float inv = rsqrtf(sq * (1.0f / 96.0f) + 1e-5f);
    float* dst = out + (size_t)tok * 96;
    dst[lane]      = d0 * inv * g[lane]      + bt[lane];
    dst[lane + 32] = d1 * inv * g[lane + 32] + bt[lane + 32];
    dst[lane + 64] = d2 * inv * g[lane + 64] + bt[lane + 64];
}

// ---------------------------------------------------------------------------
// Tall-skinny GEMM: out[m, n0+j] = act( A[m,:K] . wT[:,n0+j] + bias ) (+ modes)
// Block tile: 64 rows x 96 cols, thread tile 4x6. K chunked by 32.
// MODE 0: plain store (out has outN cols)
// MODE 1: proj epilogue: roll(+4,+4) scatter + residual from `res` (x)
// MODE 2: residual add at same index (final fc2 -> d_out)
// ACT 0: none, 1: gelu
// ---------------------------------------------------------------------------
template<int ACT, int MODE>
__global__ void gemm_kernel(const float* __restrict__ A, const float* __restrict__ wT,
                            const float* __restrict__ bias, const float* __restrict__ res,
                            float* __restrict__ out, int M, int K, int Nld, int n0_off, int outN)
{
    __shared__ float As[32][65];
    __shared__ float Ws[32][96];
    int m0 = blockIdx.x * 64;
    int n0 = (blockIdx.y + n0_off) * 96;
    int t  = threadIdx.x;
    int pg = t & 15,  cg = t >> 4;
    int r0 = pg * 4,  c0 = cg * 6;
    float acc[4][6];
    #pragma unroll
    for (int p = 0; p < 4; p++)
        #pragma unroll
        for (int j = 0; j < 6; j++) acc[p][j] = 0.0f;

    for (int k0 = 0; k0 < K; k0 += 32) {
        int col = t & 31, rb = t >> 5;
        #pragma unroll
        for (int i = 0; i < 8; i++) {
            int r = rb + i * 8;
            As[col][r] = A[(size_t)(m0 + r) * K + k0 + col];
        }
        #pragma unroll
        for (int i = 0; i < 12; i++) {
            int idx = t + i * 256;
            int kk = idx / 96, cc = idx % 96;
            Ws[kk][cc] = wT[(size_t)(k0 + kk) * Nld + n0 + cc];
        }
        __syncthreads();
        #pragma unroll
        for (int kk = 0; kk < 32; kk++) {
            float a[4], w[6];
            #pragma unroll
            for (int p = 0; p < 4; p++) a[p] = As[kk][r0 + p];
            #pragma unroll
            for (int j = 0; j < 6; j++) w[j] = Ws[kk][c0 + j];
            #pragma unroll
            for (int p = 0; p < 4; p++)
                #pragma unroll
                for (int j = 0; j < 6; j++) acc[p][j] += a[p] * w[j];
        }
        __syncthreads();
    }

    #pragma unroll
    for (int p = 0; p < 4; p++) {
        int row = m0 + r0 + p;
        #pragma unroll
        for (int j = 0; j < 6; j++) {
            int c = c0 + j;
            float v = acc[p][j] + bias[n0 + c];
            if (ACT == 1) v = gelu_f(v);
            if (MODE == 0) {
                out[(size_t)row * outN + n0 + c] = v;
            } else if (MODE == 1) {
                int bb = row >> 16, rr = row & 65535, hy = rr >> 8, wx = rr & 255;
                int tr = (bb << 16) | (((hy + 4) & 255) << 8) | ((wx + 4) & 255);
                out[(size_t)tr * 96 + c] = res[(size_t)tr * 96 + c] + v;
            } else {
                out[(size_t)row * 96 + c] = res[(size_t)row * 96 + c] + v;
            }
        }
    }
}

// ---------------------------------------------------------------------------
// 3x3 SAME conv, NHWC. Block = 8x8 pixel tile x all COUT channels.
// Thread tile: 4 pixels x (COUT/16) channels. ci chunked by KC.
// ACT: 0 none, 1 relu, 2 gelu.  RES: add res[] at same location.
// ---------------------------------------------------------------------------
template<int CIN, int COUT, int KC, int ACT, int RES>
__global__ void conv3x3_kernel(const float* __restrict__ in, const float* __restrict__ w,
                               const float* __restrict__ bias, const float* __restrict__ res,
                               float* __restrict__ out)
{
    __shared__ float ins[KC][100];
    __shared__ float ws[9][KC][COUT];
    constexpr int CoPer = COUT / 16;
    int x0 = blockIdx.x * 8, y0 = blockIdx.y * 8, b = blockIdx.z;
    int t  = threadIdx.x;
    int pg = t & 15, cg = t >> 4;
    int c0 = cg * CoPer;
    int ly[4], lx[4], pixb[4];
    #pragma unroll
    for (int p = 0; p < 4; p++) {
        int q = pg * 4 + p;
        ly[p] = q >> 3; lx[p] = q & 7;
        pixb[p] = ly[p] * 10 + lx[p];
    }
    float acc[4][CoPer];
    #pragma unroll
    for (int p = 0; p < 4; p++)
        #pragma unroll
        for (int j = 0; j < CoPer; j++) acc[p][j] = 0.0f;

    for (int ci0 = 0; ci0 < CIN; ci0 += KC) {
        for (int idx = t; idx < 100 * KC; idx += 256) {
            int pix = idx / KC, ci = idx % KC;
            int gy = y0 + pix / 10 - 1, gx = x0 + pix % 10 - 1;
            float v = 0.0f;
            if ((unsigned)gy < 256u && (unsigned)gx < 256u)
                v = in[(size_t)((b << 16) | (gy << 8) | gx) * CIN + ci0 + ci];
            ins[ci][pix] = v;
        }
        for (int idx = t; idx < 9 * KC * COUT; idx += 256) {
            int co = idx % COUT;
            int r2 = idx / COUT;
            int ci = r2 % KC, tap = r2 / KC;
            ws[tap][ci][co] = w[((size_t)(tap * CIN + ci0 + ci)) * COUT + co];
        }
        __syncthreads();
        #pragma unroll 2
        for (int ci = 0; ci < KC; ci++) {
            #pragma unroll
            for (int dy = 0; dy < 3; dy++) {
                #pragma unroll
                for (int dx = 0; dx < 3; dx++) {
                    float av[4];
                    #pragma unroll
                    for (int p = 0; p < 4; p++) av[p] = ins[ci][pixb[p] + dy * 10 + dx];
                    const float* wrow = &ws[dy * 3 + dx][ci][c0];
                    #pragma unroll
                    for (int j = 0; j < CoPer; j++) {
                        float wv = wrow[j];
                        #pragma unroll
                        for (int p = 0; p < 4; p++) acc[p][j] += av[p] * wv;
                    }
                }
            }
        }
        __syncthreads();
    }

    #pragma unroll
    for (int p = 0; p < 4; p++) {
        int y = y0 + ly[p], x = x0 + lx[p];
        size_t base = (size_t)((b << 16) | (y << 8) | x) * COUT;
        #pragma unroll
        for (int j = 0; j < CoPer; j++) {
            int co = c0 + j;
            float v = acc[p][j] + bias[co];
            if (ACT == 1) v = fmaxf(v, 0.0f);
            if (ACT == 2) v = gelu_f(v);
            if (RES) v += res[base + co];
            out[base + co] = v;
        }
    }
}

// ---------------------------------------------------------------------------
// Windowed dual attention. One block per (window, head). 64 threads = rows.
// ---------------------------------------------------------------------------
DEV int regio(int wblk, int i) { return (wblk < 31) ? 0 : ((i < 4) ? 1 : 2); }

DEV void attn_pass(const float4 (*K4)[4], const float4 (*V4)[4], const float4 q[4],
                   float lsv, const float* rpb_s, int i1, int j1, int cnt1,
                   int wh, int ww, float4 o[4])
{
    float s[64];
    #pragma unroll
    for (int m = 0; m < 64; m++) {
        const float4* kr = K4[m];
        float d;
        d  = q[0].x * kr[0].x + q[0].y * kr[0].y + q[0].z * kr[0].z + q[0].w * kr[0].w;
        d += q[1].x * kr[1].x + q[1].y * kr[1].y + q[1].z * kr[1].z + q[1].w * kr[1].w;
        d += q[2].x * kr[2].x + q[2].y * kr[2].y + q[2].z * kr[2].z + q[2].w * kr[2].w;
        d += q[3].x * kr[3].x + q[3].y * kr[3].y + q[3].z * kr[3].z + q[3].w * kr[3].w;
        int i2 = m >> 3, j2 = m & 7;
        float rb = rpb_s[(i1 - i2 + 7) * 15 + (j1 - j2 + 7)];
        int cnt2 = regio(wh, i2) * 3 + regio(ww, j2);
        s[m] = d * lsv + rb + ((cnt1 != cnt2) ? -100.0f : 0.0f);
    }
    float mx = s[0];
    #pragma unroll
    for (int m = 1; m < 64; m++) mx = fmaxf(mx, s[m]);
    float sum = 0.0f;
    float4 a0 = make_float4(0, 0, 0, 0), a1 = a0, a2 = a0, a3 = a0;
    #pragma unroll
    for (int m = 0; m < 64; m++) {
        float p = expf(s[m] - mx);
        sum += p;
        const float4* vr = V4[m];
        a0.x += p * vr[0].x; a0.y += p * vr[0].y; a0.z += p * vr[0].z; a0.w += p * vr[0].w;
        a1.x += p * vr[1].x; a1.y += p * vr[1].y; a1.z += p * vr[1].z; a1.w += p * vr[1].w;
        a2.x += p * vr[2].x; a2.y += p * vr[2].y; a2.z += p * vr[2].z; a2.w += p * vr[2].w;
        a3.x += p * vr[3].x; a3.y += p * vr[3].y; a3.z += p * vr[3].z; a3.w += p * vr[3].w;
    }
    float inv = 1.0f / sum;
    o[0] = make_float4(a0.x * inv, a0.y * inv, a0.z * inv, a0.w * inv);
    o[1] = make_float4(a1.x * inv, a1.y * inv, a1.z * inv, a1.w * inv);
    o[2] = make_float4(a2.x * inv, a2.y * inv, a2.z * inv, a2.w * inv);
    o[3] = make_float4(a3.x * inv, a3.y * inv, a3.z * inv, a3.w * inv);
}

__global__ void attn_kernel(const float* __restrict__ qkvx, const float* __restrict__ qkvr,
                            const float* __restrict__ lsp, const float* __restrict__ gat,
                            const float* __restrict__ rpbt, float* __restrict__ out)
{
    __shared__ float4 ks[64][4], vs[64][4], krs[64][4], vrs[64][4];
    __shared__ float rpb_s[225];
    int blk  = blockIdx.x;
    int head = blk % HEADS;
    int widx = blk / HEADS;
    int b  = widx >> 10;
    int nw = widx & 1023;
    int wh = nw >> 5, ww = nw & 31;
    int n  = threadIdx.x;
    int i1 = n >> 3, j1 = n & 7;

    size_t tok = (size_t)((b << 16) | ((wh * 8 + i1) << 8) | (ww * 8 + j1));
    size_t rowbase = tok * 288 + head * 16;

    // q (normalized, kept in registers)
    float4 q[4];
    {
        const float4* qp = (const float4*)(qkvx + rowbase);
        q[0] = qp[0]; q[1] = qp[1]; q[2] = qp[2]; q[3] = qp[3];
        float ss = 0.0f;
        #pragma unroll
        for (int i = 0; i < 4; i++)
            ss += q[i].x * q[i].x + q[i].y * q[i].y + q[i].z * q[i].z + q[i].w * q[i].w;
        float inv = 1.0f / fmaxf(sqrtf(ss), 1e-12f);
        #pragma unroll
        for (int i = 0; i < 4; i++) { q[i].x *= inv; q[i].y *= inv; q[i].z *= inv; q[i].w *= inv; }
    }
    // k (normalized), v
    {
        const float4* kp = (const float4*)(qkvx + rowbase + 96);
        float4 kv[4] = {kp[0], kp[1], kp[2], kp[3]};
        float ss = 0.0f;
        #pragma unroll
        for (int i = 0; i < 4; i++)
            ss += kv[i].x * kv[i].x + kv[i].y * kv[i].y + kv[i].z * kv[i].z + kv[i].w * kv[i].w;
        float inv = 1.0f / fmaxf(sqrtf(ss), 1e-12f);
        #pragma unroll
        for (int i = 0; i < 4; i++)
            ks[n][i] = make_float4(kv[i].x * inv, kv[i].y * inv, kv[i].z * inv, kv[i].w * inv);
        const float4* vp = (const float4*)(qkvx + rowbase + 192);
        #pragma unroll
        for (int i = 0; i < 4; i++) vs[n][i] = vp[i];
    }
    // k_r (normalized), v_r
    {
        const float4* kp = (const float4*)(qkvr + rowbase + 96);
        float4 kv[4] = {kp[0], kp[1], kp[2], kp[3]};
        float ss = 0.0f;
        #pragma unroll
        for (int i = 0; i < 4; i++)
            ss += kv[i].x * kv[i].x + kv[i].y * kv[i].y + kv[i].z * kv[i].z + kv[i].w * kv[i].w;
        float inv = 1.0f / fmaxf(sqrtf(ss), 1e-12f);
        #pragma unroll
        for (int i = 0; i < 4; i++)
            krs[n][i] = make_float4(kv[i].x * inv, kv[i].y * inv, kv[i].z * inv, kv[i].w * inv);
        const float4* vp = (const float4*)(qkvr + rowbase + 192);
        #pragma unroll
        for (int i = 0; i < 4; i++) vrs[n][i] = vp[i];
    }
    for (int idx = n; idx < 225; idx += 64) rpb_s[idx] = rpbt[idx * 6 + head];

    float lsv = expf(fminf(lsp[head], 4.605170185988092f));   // log(100)
    float gv  = 1.0f / (1.0f + expf(-gat[head]));
    int cnt1 = regio(wh, i1) * 3 + regio(ww, j1);
    __syncthreads();

    float4 o1[4], o2[4];
    attn_pass(ks,  vs,  q, lsv, rpb_s, i1, j1, cnt1, wh, ww, o1);
    attn_pass(krs, vrs, q, lsv, rpb_s, i1, j1, cnt1, wh, ww, o2);

    float4* op = (float4*)(out + tok * 96 + head * 16);
    float og = 1.0f - gv;
    #pragma unroll
    for (int i = 0; i < 4; i++)
        op[i] = make_float4(og * o1[i].x + gv * o2[i].x,
                            og * o1[i].y + gv * o2[i].y,
                            og * o1[i].z + gv * o2[i].z,
                            og * o1[i].w + gv * o2[i].w);
}

// ---------------------------------------------------------------------------
// Host orchestration
// ---------------------------------------------------------------------------
extern "C" void kernel_launch(void* const* d_in, const int* in_sizes, int n_in,
                              void* d_out, int out_size)
{
    const float* x       = (const float*)d_in[0];
    const float* ref     = (const float*)d_in[1];
    const float* n1g     = (const float*)d_in[2];
    const float* n1b     = (const float*)d_in[3];
    const float* qkv_w   = (const float*)d_in[4];
    const float* qkv_b   = (const float*)d_in[5];
    const float* lscale  = (const float*)d_in[6];
    const float* gating  = (const float*)d_in[7];
    const float* rpbt    = (const float*)d_in[8];
    const float* trunk_w = (const float*)d_in[9];
    const float* trunk_b = (const float*)d_in[10];
    const float* proj_w  = (const float*)d_in[11];
    const float* proj_b  = (const float*)d_in[12];
    const float* n2g     = (const float*)d_in[13];
    const float* n2b     = (const float*)d_in[14];
    const float* fc1_w   = (const float*)d_in[15];
    const float* fc1_b   = (const float*)d_in[16];
    const float* convm_w = (const float*)d_in[17];
    const float* convm_b = (const float*)d_in[18];
    const float* fc2_w   = (const float*)d_in[19];
    const float* fc2_b   = (const float*)d_in[20];
    float* out = (float*)d_out;

    float *lnx, *lnr, *qkvx, *qkvr, *ybuf, *tmp, *x2, *h1, *h2;
    float *qkvT, *projT, *fc1T, *fc2T;
    cudaGetSymbolAddress((void**)&lnx,  g_lnx);
    cudaGetSymbolAddress((void**)&lnr,  g_lnr);
    cudaGetSymbolAddress((void**)&qkvx, g_qkvx);
    cudaGetSymbolAddress((void**)&qkvr, g_qkvr);
    cudaGetSymbolAddress((void**)&ybuf, g_y);
    cudaGetSymbolAddress((void**)&tmp,  g_tmp);
    cudaGetSymbolAddress((void**)&x2,   g_x2);
    cudaGetSymbolAddress((void**)&h1,   g_h1);
    cudaGetSymbolAddress((void**)&h2,   g_h2);
    cudaGetSymbolAddress((void**)&qkvT, g_qkv_wT);
    cudaGetSymbolAddress((void**)&projT,g_proj_wT);
    cudaGetSymbolAddress((void**)&fc1T, g_fc1_wT);
    cudaGetSymbolAddress((void**)&fc2T, g_fc2_wT);

    // Weight transposes (out,in) -> (in,out)
    transpose_k<<<(288 * 96 + 255) / 256, 256>>>(qkv_w, qkvT, 288, 96);
    transpose_k<<<(96 * 96 + 255) / 256, 256>>>(proj_w, projT, 96, 96);
    transpose_k<<<(192 * 96 + 255) / 256, 256>>>(fc1_w, fc1T, 192, 96);
    transpose_k<<<(96 * 192 + 255) / 256, 256>>>(fc2_w, fc2T, 96, 192);

    // LN1 + roll(-4,-4) for both images
    ln_kernel<<<TOK / 8, 256>>>(x,   n1g, n1b, lnx, 4);
    ln_kernel<<<TOK / 8, 256>>>(ref, n1g, n1b, lnr, 4);

    // QKV GEMMs (ref only needs k,v -> col blocks 1,2)
    gemm_kernel<0, 0><<<dim3(TOK / 64, 3), 256>>>(lnx, qkvT, qkv_b, nullptr, qkvx, TOK, 96, 288, 0, 288);
    gemm_kernel<0, 0><<<dim3(TOK / 64, 2), 256>>>(lnr, qkvT, qkv_b, nullptr, qkvr, TOK, 96, 288, 1, 288);

    // Windowed dual attention -> ybuf (rolled coords, window-reversed)
    attn_kernel<<<Bb * 1024 * HEADS, 64>>>(qkvx, qkvr, lscale, gating, rpbt, ybuf);

    // Trunk: two residual conv blocks (on rolled image, SAME padding)
    conv3x3_kernel<96, 96, 8, 1, 0><<<dim3(32, 32, Bb), 256>>>(ybuf, trunk_w,              trunk_b,       nullptr, tmp);
    conv3x3_kernel<96, 96, 8, 0, 1><<<dim3(32, 32, Bb), 256>>>(tmp,  trunk_w + 1 * 82944, trunk_b + 96,  ybuf,    ybuf);
    conv3x3_kernel<96, 96, 8, 1, 0><<<dim3(32, 32, Bb), 256>>>(ybuf, trunk_w + 2 * 82944, trunk_b + 192, nullptr, tmp);
    conv3x3_kernel<96, 96, 8, 0, 1><<<dim3(32, 32, Bb), 256>>>(tmp,  trunk_w + 3 * 82944, trunk_b + 288, ybuf,    ybuf);

    // proj + roll(+4,+4) + shortcut  ->  x2
    gemm_kernel<0, 1><<<dim3(TOK / 64, 1), 256>>>(ybuf, projT, proj_b, x, x2, TOK, 96, 96, 0, 96);

    // LN2 -> tmp, fc1+gelu -> h1, convm+gelu -> h2, fc2 + residual -> out
    ln_kernel<<<TOK / 8, 256>>>(x2, n2g, n2b, tmp, 0);
    gemm_kernel<1, 0><<<dim3(TOK / 64, 2), 256>>>(tmp, fc1T, fc1_b, nullptr, h1, TOK, 96, 192, 0, 192);
    conv3x3_kernel<192, 192, 4, 2, 0><<<dim3(32, 32, Bb), 256>>>(h1, convm_w, convm_b, nullptr, h2);
    gemm_kernel<0, 2><<<dim3(TOK / 64, 1), 256>>>(h2, fc2T, fc2_b, x2, out, TOK, 192, 96, 0, 96);
}

// round 2
// speedup vs baseline: 1.1686x; 1.1686x over previous
#include <cuda_runtime.h>
#include <math.h>

// ---------------------------------------------------------------------------
// Problem constants
// ---------------------------------------------------------------------------
constexpr int Bb   = 2;
constexpr int Cc   = 96;
constexpr int HEADS= 6;
constexpr int HID  = 192;
constexpr int TOK  = Bb * 256 * 256;          // 131072 tokens

// ---------------------------------------------------------------------------
// Static device scratch
// ---------------------------------------------------------------------------
__device__ float g_lnx [TOK * Cc];
__device__ float g_lnr [TOK * Cc];
__device__ float g_qkvx[TOK * 288];
__device__ float g_qkvr[TOK * 288];
__device__ float g_y   [TOK * Cc];
__device__ float g_tmp [TOK * Cc];
__device__ float g_x2  [TOK * Cc];
__device__ float g_h1  [TOK * HID];
__device__ float g_h2  [TOK * HID];
__device__ float g_qkv_wT[96 * 288];
__device__ float g_proj_wT[96 * 96];
__device__ float g_fc1_wT[96 * 192];
__device__ float g_fc2_wT[192 * 96];

#define DEV __device__ __forceinline__
typedef unsigned long long u64;

DEV float gelu_f(float v) { return 0.5f * v * (1.0f + erff(v * 0.70710678118654752f)); }

// ------------------------- f32x2 helpers -----------------------------------
DEV u64 dup2(float v) {
    u64 r; unsigned x = __float_as_uint(v);
    asm("mov.b64 %0, {%1, %1};" : "=l"(r) : "r"(x));
    return r;
}
DEV u64 lds2(const float* p) {   // 8B-aligned shared load of a float pair
    return *reinterpret_cast<const u64*>(p);
}
DEV void ffma2(u64& d, u64 a, u64 b) {
    asm("fma.rn.f32x2 %0, %1, %2, %3;" : "=l"(d) : "l"(a), "l"(b), "l"(d));
}
DEV float2 unpk(u64 v) {
    unsigned lo, hi;
    asm("mov.b64 {%0, %1}, %2;" : "=r"(lo), "=r"(hi) : "l"(v));
    return make_float2(__uint_as_float(lo), __uint_as_float(hi));
}

// ---------------------------------------------------------------------------
// Tiny transpose: dst[c*R + r] = src[r*C + c]
// ---------------------------------------------------------------------------
__global__ void transpose_k(const float* __restrict__ src, float* __restrict__ dst, int R, int C)
{
    int i = blockIdx.x * 256 + threadIdx.x;
    if (i < R * C) {
        int r = i / C, c = i % C;
        dst[c * R + r] = src[i];
    }
}

// ---------------------------------------------------------------------------
// LayerNorm over C=96, with optional (+shift,+shift) gather (implements roll)
// ---------------------------------------------------------------------------
__global__ void ln_kernel(const float* __restrict__ in, const float* __restrict__ g,
                          const float* __restrict__ bt, float* __restrict__ out, int shift)
{
    int gid  = blockIdx.x * blockDim.x + threadIdx.x;
    int tok  = gid >> 5;
    int lane = gid & 31;
    if (tok >= TOK) return;
    int b = tok >> 16, rr = tok & 65535, h = rr >> 8, w = rr & 255;
    const float* src = in + (size_t)((b << 16) | (((h + shift) & 255) << 8) | ((w + shift) & 255)) * 96;
    float v0 = src[lane], v1 = src[lane + 32], v2 = src[lane + 64];
    float s = v0 + v1 + v2;
    #pragma unroll
    for (int o = 16; o > 0; o >>= 1) s += __shfl_xor_sync(0xffffffffu, s, o);
    float mu = s * (1.0f / 96.0f);
    float d0 = v0 - mu, d1 = v1 - mu, d2 = v2 - mu;
    float sq = d0 * d0 + d1 * d1 + d2 * d2;
    #pragma unroll
    for (int o = 16; o > 0; o >>= 1) sq += __shfl_xor_sync(0xffffffffu, sq, o);
    float inv = rsqrtf(sq * (1.0f / 96.0f) + 1e-5f);
    float* dst = out + (size_t)tok * 96;
    dst[lane]      = d0 * inv * g[lane]      + bt[lane];
    dst[lane + 32] = d1 * inv * g[lane + 32] + bt[lane + 32];
    dst[lane + 64] = d2 * inv * g[lane + 64] + bt[lane + 64];
}

// ---------------------------------------------------------------------------
// Tall-skinny GEMM with f32x2 inner product.
// Block tile 64 rows x 96 cols, thread tile 4 px x 6 ch (3 f32x2 pairs).
// MODE 0 plain, 1 proj(roll+res), 2 residual. ACT 0 none, 1 gelu.
// ---------------------------------------------------------------------------
template<int ACT, int MODE>
__global__ void __launch_bounds__(256) gemm_kernel(
        const float* __restrict__ A, const float* __restrict__ wT,
        const float* __restrict__ bias, const float* __restrict__ res,
        float* __restrict__ out, int M, int K, int Nld, int n0_off, int outN)
{
    __shared__ __align__(16) float As[32][65];
    __shared__ __align__(16) float Ws[32][96];
    int m0 = blockIdx.x * 64;
    int n0 = (blockIdx.y + n0_off) * 96;
    int t  = threadIdx.x;
    int pg = t & 15,  cg = t >> 4;
    int r0 = pg * 4,  c0 = cg * 6;
    u64 acc[4][3];
    #pragma unroll
    for (int p = 0; p < 4; p++)
        #pragma unroll
        for (int j = 0; j < 3; j++) acc[p][j] = 0ull;

    for (int k0 = 0; k0 < K; k0 += 32) {
        int col = t & 31, rb = t >> 5;
        #pragma unroll
        for (int i = 0; i < 8; i++) {
            int r = rb + i * 8;
            As[col][r] = A[(size_t)(m0 + r) * K + k0 + col];
        }
        #pragma unroll
        for (int i = 0; i < 12; i++) {
            int idx = t + i * 256;
            int kk = idx / 96, cc = idx % 96;
            Ws[kk][cc] = wT[(size_t)(k0 + kk) * Nld + n0 + cc];
        }
        __syncthreads();
        #pragma unroll
        for (int kk = 0; kk < 32; kk++) {
            u64 a2[4], w2[3];
            #pragma unroll
            for (int p = 0; p < 4; p++) a2[p] = dup2(As[kk][r0 + p]);
            #pragma unroll
            for (int j = 0; j < 3; j++) w2[j] = lds2(&Ws[kk][c0 + 2 * j]);
            #pragma unroll
            for (int p = 0; p < 4; p++)
                #pragma unroll
                for (int j = 0; j < 3; j++) ffma2(acc[p][j], a2[p], w2[j]);
        }
        __syncthreads();
    }

    #pragma unroll
    for (int p = 0; p < 4; p++) {
        int row = m0 + r0 + p;
        #pragma unroll
        for (int j = 0; j < 3; j++) {
            float2 f = unpk(acc[p][j]);
            #pragma unroll
            for (int h = 0; h < 2; h++) {
                int c = c0 + 2 * j + h;
                float v = (h ? f.y : f.x) + bias[n0 + c];
                if (ACT == 1) v = gelu_f(v);
                if (MODE == 0) {
                    out[(size_t)row * outN + n0 + c] = v;
                } else if (MODE == 1) {
                    int bb = row >> 16, rr = row & 65535, hy = rr >> 8, wx = rr & 255;
                    int tr = (bb << 16) | (((hy + 4) & 255) << 8) | ((wx + 4) & 255);
                    out[(size_t)tr * 96 + c] = res[(size_t)tr * 96 + c] + v;
                } else {
                    out[(size_t)row * 96 + c] = res[(size_t)row * 96 + c] + v;
                }
            }
        }
    }
}

// ---------------------------------------------------------------------------
// 3x3 SAME conv, NHWC, f32x2 inner product.
// Block = 8x8 pixel tile x COUT. Thread: 4 consecutive px x CoPer channels.
// Input rows hoisted out of tap loop; pixel values duplicated once per ci.
// ---------------------------------------------------------------------------
template<int CIN, int COUT, int KC, int ACT, int RES>
__global__ void __launch_bounds__(256) conv3x3_kernel(
        const float* __restrict__ in, const float* __restrict__ w,
        const float* __restrict__ bias, const float* __restrict__ res,
        float* __restrict__ out)
{
    __shared__ __align__(16) float ins[KC][100];
    __shared__ __align__(16) float ws[9][KC][COUT];
    constexpr int CoPer = COUT / 16;
    constexpr int CP    = CoPer / 2;
    int x0 = blockIdx.x * 8, y0 = blockIdx.y * 8, b = blockIdx.z;
    int t  = threadIdx.x;
    int pg = t & 15, cg = t >> 4;
    int c0 = cg * CoPer;
    int q0 = pg * 4;
    int ly = q0 >> 3, lx0 = q0 & 7;          // 4 consecutive pixels in one row

    u64 acc[4][CP];
    #pragma unroll
    for (int p = 0; p < 4; p++)
        #pragma unroll
        for (int j = 0; j < CP; j++) acc[p][j] = 0ull;

    for (int ci0 = 0; ci0 < CIN; ci0 += KC) {
        for (int idx = t; idx < 100 * KC; idx += 256) {
            int pix = idx / KC, ci = idx % KC;
            int gy = y0 + pix / 10 - 1, gx = x0 + pix % 10 - 1;
            float v = 0.0f;
            if ((unsigned)gy < 256u && (unsigned)gx < 256u)
                v = in[(size_t)((b << 16) | (gy << 8) | gx) * CIN + ci0 + ci];
            ins[ci][pix] = v;
        }
        for (int idx = t; idx < 9 * KC * COUT; idx += 256) {
            int co = idx % COUT;
            int r2 = idx / COUT;
            int ci = r2 % KC, tap = r2 / KC;
            ws[tap][ci][co] = w[((size_t)(tap * CIN + ci0 + ci)) * COUT + co];
        }
        __syncthreads();
        #pragma unroll 1
        for (int ci = 0; ci < KC; ci++) {
            // hoisted input rows: 3 rows x 6 values, each duplicated into f32x2
            u64 av[3][6];
            #pragma unroll
            for (int dy = 0; dy < 3; dy++) {
                const float* rp = &ins[ci][(ly + dy) * 10 + lx0];
                float2 v0 = unpk(lds2(rp));
                float2 v1 = unpk(lds2(rp + 2));
                float2 v2 = unpk(lds2(rp + 4));
                av[dy][0] = dup2(v0.x); av[dy][1] = dup2(v0.y);
                av[dy][2] = dup2(v1.x); av[dy][3] = dup2(v1.y);
                av[dy][4] = dup2(v2.x); av[dy][5] = dup2(v2.y);
            }
            #pragma unroll
            for (int dy = 0; dy < 3; dy++) {
                #pragma unroll
                for (int dx = 0; dx < 3; dx++) {
                    const float* wp = &ws[dy * 3 + dx][ci][c0];
                    u64 w2[CP];
                    #pragma unroll
                    for (int j = 0; j < CP; j++) w2[j] = lds2(wp + 2 * j);
                    #pragma unroll
                    for (int p = 0; p < 4; p++) {
                        u64 a = av[dy][p + dx];
                        #pragma unroll
                        for (int j = 0; j < CP; j++) ffma2(acc[p][j], a, w2[j]);
                    }
                }
            }
        }
        __syncthreads();
    }

    #pragma unroll
    for (int p = 0; p < 4; p++) {
        int y = y0 + ly, x = x0 + lx0 + p;
        size_t base = (size_t)((b << 16) | (y << 8) | x) * COUT;
        #pragma unroll
        for (int j = 0; j < CP; j++) {
            float2 f = unpk(acc[p][j]);
            #pragma unroll
            for (int h = 0; h < 2; h++) {
                int co = c0 + 2 * j + h;
                float v = (h ? f.y : f.x) + bias[co];
                if (ACT == 1) v = fmaxf(v, 0.0f);
                if (ACT == 2) v = gelu_f(v);
                if (RES) v += res[base + co];
                out[base + co] = v;
            }
        }
    }
}

// ---------------------------------------------------------------------------
// Windowed dual attention. One block per (window, head). 64 threads = rows.
// ---------------------------------------------------------------------------
DEV int regio(int wblk, int i) { return (wblk < 31) ? 0 : ((i < 4) ? 1 : 2); }

DEV void attn_pass(const float4 (*K4)[4], const float4 (*V4)[4], const float4 q[4],
                   float lsv, const float* rpb_s, int i1, int j1, int cnt1,
                   int wh, int ww, float4 o[4])
{
    float s[64];
    #pragma unroll
    for (int m = 0; m < 64; m++) {
        const float4* kr = K4[m];
        float d;
        d  = q[0].x * kr[0].x + q[0].y * kr[0].y + q[0].z * kr[0].z + q[0].w * kr[0].w;
        d += q[1].x * kr[1].x + q[1].y * kr[1].y + q[1].z * kr[1].z + q[1].w * kr[1].w;
        d += q[2].x * kr[2].x + q[2].y * kr[2].y + q[2].z * kr[2].z + q[2].w * kr[2].w;
        d += q[3].x * kr[3].x + q[3].y * kr[3].y + q[3].z * kr[3].z + q[3].w * kr[3].w;
        int i2 = m >> 3, j2 = m & 7;
        float rb = rpb_s[(i1 - i2 + 7) * 15 + (j1 - j2 + 7)];
        int cnt2 = regio(wh, i2) * 3 + regio(ww, j2);
        s[m] = d * lsv + rb + ((cnt1 != cnt2) ? -100.0f : 0.0f);
    }
    float mx = s[0];
    #pragma unroll
    for (int m = 1; m < 64; m++) mx = fmaxf(mx, s[m]);
    float sum = 0.0f;
    float4 a0 = make_float4(0, 0, 0, 0), a1 = a0, a2 = a0, a3 = a0;
    #pragma unroll
    for (int m = 0; m < 64; m++) {
        float p = expf(s[m] - mx);
        sum += p;
        const float4* vr = V4[m];
        a0.x += p * vr[0].x; a0.y += p * vr[0].y; a0.z += p * vr[0].z; a0.w += p * vr[0].w;
        a1.x += p * vr[1].x; a1.y += p * vr[1].y; a1.z += p * vr[1].z; a1.w += p * vr[1].w;
        a2.x += p * vr[2].x; a2.y += p * vr[2].y; a2.z += p * vr[2].z; a2.w += p * vr[2].w;
        a3.x += p * vr[3].x; a3.y += p * vr[3].y; a3.z += p * vr[3].z; a3.w += p * vr[3].w;
    }
    float inv = 1.0f / sum;
    o[0] = make_float4(a0.x * inv, a0.y * inv, a0.z * inv, a0.w * inv);
    o[1] = make_float4(a1.x * inv, a1.y * inv, a1.z * inv, a1.w * inv);
    o[2] = make_float4(a2.x * inv, a2.y * inv, a2.z * inv, a2.w * inv);
    o[3] = make_float4(a3.x * inv, a3.y * inv, a3.z * inv, a3.w * inv);
}

__global__ void attn_kernel(const float* __restrict__ qkvx, const float* __restrict__ qkvr,
                            const float* __restrict__ lsp, const float* __restrict__ gat,
                            const float* __restrict__ rpbt, float* __restrict__ out)
{
    __shared__ float4 ks[64][4], vs[64][4], krs[64][4], vrs[64][4];
    __shared__ float rpb_s[225];
    int blk  = blockIdx.x;
    int head = blk % HEADS;
    int widx = blk / HEADS;
    int b  = widx >> 10;
    int nw = widx & 1023;
    int wh = nw >> 5, ww = nw & 31;
    int n  = threadIdx.x;
    int i1 = n >> 3, j1 = n & 7;

    size_t tok = (size_t)((b << 16) | ((wh * 8 + i1) << 8) | (ww * 8 + j1));
    size_t rowbase = tok * 288 + head * 16;

    float4 q[4];
    {
        const float4* qp = (const float4*)(qkvx + rowbase);
        q[0] = qp[0]; q[1] = qp[1]; q[2] = qp[2]; q[3] = qp[3];
        float ss = 0.0f;
        #pragma unroll
        for (int i = 0; i < 4; i++)
            ss += q[i].x * q[i].x + q[i].y * q[i].y + q[i].z * q[i].z + q[i].w * q[i].w;
        float inv = 1.0f / fmaxf(sqrtf(ss), 1e-12f);
        #pragma unroll
        for (int i = 0; i < 4; i++) { q[i].x *= inv; q[i].y *= inv; q[i].z *= inv; q[i].w *= inv; }
    }
    {
        const float4* kp = (const float4*)(qkvx + rowbase + 96);
        float4 kv[4] = {kp[0], kp[1], kp[2], kp[3]};
        float ss = 0.0f;
        #pragma unroll
        for (int i = 0; i < 4; i++)
            ss += kv[i].x * kv[i].x + kv[i].y * kv[i].y + kv[i].z * kv[i].z + kv[i].w * kv[i].w;
        float inv = 1.0f / fmaxf(sqrtf(ss), 1e-12f);
        #pragma unroll
        for (int i = 0; i < 4; i++)
            ks[n][i] = make_float4(kv[i].x * inv, kv[i].y * inv, kv[i].z * inv, kv[i].w * inv);
        const float4* vp = (const float4*)(qkvx + rowbase + 192);
        #pragma unroll
        for (int i = 0; i < 4; i++) vs[n][i] = vp[i];
    }
    {
        const float4* kp = (const float4*)(qkvr + rowbase + 96);
        float4 kv[4] = {kp[0], kp[1], kp[2], kp[3]};
        float ss = 0.0f;
        #pragma unroll
        for (int i = 0; i < 4; i++)
            ss += kv[i].x * kv[i].x + kv[i].y * kv[i].y + kv[i].z * kv[i].z + kv[i].w * kv[i].w;
        float inv = 1.0f / fmaxf(sqrtf(ss), 1e-12f);
        #pragma unroll
        for (int i = 0; i < 4; i++)
            krs[n][i] = make_float4(kv[i].x * inv, kv[i].y * inv, kv[i].z * inv, kv[i].w * inv);
        const float4* vp = (const float4*)(qkvr + rowbase + 192);
        #pragma unroll
        for (int i = 0; i < 4; i++) vrs[n][i] = vp[i];
    }
    for (int idx = n; idx < 225; idx += 64) rpb_s[idx] = rpbt[idx * 6 + head];

    float lsv = expf(fminf(lsp[head], 4.605170185988092f));
    float gv  = 1.0f / (1.0f + expf(-gat[head]));
    int cnt1 = regio(wh, i1) * 3 + regio(ww, j1);
    __syncthreads();

    float4 o1[4], o2[4];
    attn_pass(ks,  vs,  q, lsv, rpb_s, i1, j1, cnt1, wh, ww, o1);
    attn_pass(krs, vrs, q, lsv, rpb_s, i1, j1, cnt1, wh, ww, o2);

    float4* op = (float4*)(out + tok * 96 + head * 16);
    float og = 1.0f - gv;
    #pragma unroll
    for (int i = 0; i < 4; i++)
        op[i] = make_float4(og * o1[i].x + gv * o2[i].x,
                            og * o1[i].y + gv * o2[i].y,
                            og * o1[i].z + gv * o2[i].z,
                            og * o1[i].w + gv * o2[i].w);
}

// ---------------------------------------------------------------------------
// Host orchestration
// ---------------------------------------------------------------------------
extern "C" void kernel_launch(void* const* d_in, const int* in_sizes, int n_in,
                              void* d_out, int out_size)
{
    const float* x       = (const float*)d_in[0];
    const float* ref     = (const float*)d_in[1];
    const float* n1g     = (const float*)d_in[2];
    const float* n1b     = (const float*)d_in[3];
    const float* qkv_w   = (const float*)d_in[4];
    const float* qkv_b   = (const float*)d_in[5];
    const float* lscale  = (const float*)d_in[6];
    const float* gating  = (const float*)d_in[7];
    const float* rpbt    = (const float*)d_in[8];
    const float* trunk_w = (const float*)d_in[9];
    const float* trunk_b = (const float*)d_in[10];
    const float* proj_w  = (const float*)d_in[11];
    const float* proj_b  = (const float*)d_in[12];
    const float* n2g     = (const float*)d_in[13];
    const float* n2b     = (const float*)d_in[14];
    const float* fc1_w   = (const float*)d_in[15];
    const float* fc1_b   = (const float*)d_in[16];
    const float* convm_w = (const float*)d_in[17];
    const float* convm_b = (const float*)d_in[18];
    const float* fc2_w   = (const float*)d_in[19];
    const float* fc2_b   = (const float*)d_in[20];
    float* out = (float*)d_out;

    float *lnx, *lnr, *qkvx, *qkvr, *ybuf, *tmp, *x2, *h1, *h2;
    float *qkvT, *projT, *fc1T, *fc2T;
    cudaGetSymbolAddress((void**)&lnx,  g_lnx);
    cudaGetSymbolAddress((void**)&lnr,  g_lnr);
    cudaGetSymbolAddress((void**)&qkvx, g_qkvx);
    cudaGetSymbolAddress((void**)&qkvr, g_qkvr);
    cudaGetSymbolAddress((void**)&ybuf, g_y);
    cudaGetSymbolAddress((void**)&tmp,  g_tmp);
    cudaGetSymbolAddress((void**)&x2,   g_x2);
    cudaGetSymbolAddress((void**)&h1,   g_h1);
    cudaGetSymbolAddress((void**)&h2,   g_h2);
    cudaGetSymbolAddress((void**)&qkvT, g_qkv_wT);
    cudaGetSymbolAddress((void**)&projT,g_proj_wT);
    cudaGetSymbolAddress((void**)&fc1T, g_fc1_wT);
    cudaGetSymbolAddress((void**)&fc2T, g_fc2_wT);

    transpose_k<<<(288 * 96 + 255) / 256, 256>>>(qkv_w, qkvT, 288, 96);
    transpose_k<<<(96 * 96 + 255) / 256, 256>>>(proj_w, projT, 96, 96);
    transpose_k<<<(192 * 96 + 255) / 256, 256>>>(fc1_w, fc1T, 192, 96);
    transpose_k<<<(96 * 192 + 255) / 256, 256>>>(fc2_w, fc2T, 96, 192);

    ln_kernel<<<TOK / 8, 256>>>(x,   n1g, n1b, lnx, 4);
    ln_kernel<<<TOK / 8, 256>>>(ref, n1g, n1b, lnr, 4);

    gemm_kernel<0, 0><<<dim3(TOK / 64, 3), 256>>>(lnx, qkvT, qkv_b, nullptr, qkvx, TOK, 96, 288, 0, 288);
    gemm_kernel<0, 0><<<dim3(TOK / 64, 2), 256>>>(lnr, qkvT, qkv_b, nullptr, qkvr, TOK, 96, 288, 1, 288);

    attn_kernel<<<Bb * 1024 * HEADS, 64>>>(qkvx, qkvr, lscale, gating, rpbt, ybuf);

    conv3x3_kernel<96, 96, 8, 1, 0><<<dim3(32, 32, Bb), 256>>>(ybuf, trunk_w,             trunk_b,       nullptr, tmp);
    conv3x3_kernel<96, 96, 8, 0, 1><<<dim3(32, 32, Bb), 256>>>(tmp,  trunk_w + 1 * 82944, trunk_b + 96,  ybuf,    ybuf);
    conv3x3_kernel<96, 96, 8, 1, 0><<<dim3(32, 32, Bb), 256>>>(ybuf, trunk_w + 2 * 82944, trunk_b + 192, nullptr, tmp);
    conv3x3_kernel<96, 96, 8, 0, 1><<<dim3(32, 32, Bb), 256>>>(tmp,  trunk_w + 3 * 82944, trunk_b + 288, ybuf,    ybuf);

    gemm_kernel<0, 1><<<dim3(TOK / 64, 1), 256>>>(ybuf, projT, proj_b, x, x2, TOK, 96, 96, 0, 96);

    ln_kernel<<<TOK / 8, 256>>>(x2, n2g, n2b, tmp, 0);
    gemm_kernel<1, 0><<<dim3(TOK / 64, 2), 256>>>(tmp, fc1T, fc1_b, nullptr, h1, TOK, 96, 192, 0, 192);
    conv3x3_kernel<192, 192, 4, 2, 0><<<dim3(32, 32, Bb), 256>>>(h1, convm_w, convm_b, nullptr, h2);
    gemm_kernel<0, 2><<<dim3(TOK / 64, 1), 256>>>(h2, fc2T, fc2_b, x2, out, TOK, 192, 96, 0, 96);
}

// round 4
// speedup vs baseline: 2.1618x; 1.8499x over previous
#include <cuda_runtime.h>
#include <math.h>

// ---------------------------------------------------------------------------
// Problem constants
// ---------------------------------------------------------------------------
constexpr int Bb   = 2;
constexpr int Cc   = 96;
constexpr int HEADS= 6;
constexpr int HID  = 192;
constexpr int TOK  = Bb * 256 * 256;          // 131072 tokens

// ---------------------------------------------------------------------------
// Static device scratch
// ---------------------------------------------------------------------------
__device__ float g_lnx [TOK * Cc];
__device__ float g_lnr [TOK * Cc];
__device__ float g_qkvx[TOK * 288];
__device__ float g_qkvr[TOK * 288];
__device__ float g_y   [TOK * Cc];
__device__ float g_tmp [TOK * Cc];
__device__ float g_x2  [TOK * Cc];
__device__ float g_h1  [TOK * HID];
__device__ float g_h2  [TOK * HID];
__device__ float g_qkv_wT[96 * 288];
__device__ float g_proj_wT[96 * 96];
__device__ float g_fc1_wT[96 * 192];
__device__ float g_fc2_wT[192 * 96];

#define DEV __device__ __forceinline__

DEV float gelu_f(float v) { return 0.5f * v * (1.0f + erff(v * 0.70710678118654752f)); }

DEV unsigned f2tf(float f) {
    unsigned u;
    asm("cvt.rna.tf32.f32 %0, %1;" : "=r"(u) : "f"(f));
    return u;
}

// D += A(16x8, tf32, row) * B(8x8, tf32, col)
DEV void mma_tf32(float* c, const unsigned* a, const unsigned* b) {
    asm("mma.sync.aligned.m16n8k8.row.col.f32.tf32.tf32.f32 "
        "{%0,%1,%2,%3}, {%4,%5,%6,%7}, {%8,%9}, {%0,%1,%2,%3};"
        : "+f"(c[0]), "+f"(c[1]), "+f"(c[2]), "+f"(c[3])
        : "r"(a[0]), "r"(a[1]), "r"(a[2]), "r"(a[3]), "r"(b[0]), "r"(b[1]));
}

// ---------------------------------------------------------------------------
// Tiny transpose: dst[c*R + r] = src[r*C + c]
// ---------------------------------------------------------------------------
__global__ void transpose_k(const float* __restrict__ src, float* __restrict__ dst, int R, int C)
{
    int i = blockIdx.x * 256 + threadIdx.x;
    if (i < R * C) {
        int r = i / C, c = i % C;
        dst[c * R + r] = src[i];
    }
}

// ---------------------------------------------------------------------------
// LayerNorm over C=96, with optional (+shift,+shift) gather (implements roll)
// ---------------------------------------------------------------------------
__global__ void ln_kernel(const float* __restrict__ in, const float* __restrict__ g,
                          const float* __restrict__ bt, float* __restrict__ out, int shift)
{
    int gid  = blockIdx.x * blockDim.x + threadIdx.x;
    int tok  = gid >> 5;
    int lane = gid & 31;
    if (tok >= TOK) return;
    int b = tok >> 16, rr = tok & 65535, h = rr >> 8, w = rr & 255;
    const float* src = in + (size_t)((b << 16) | (((h + shift) & 255) << 8) | ((w + shift) & 255)) * 96;
    float v0 = src[lane], v1 = src[lane + 32], v2 = src[lane + 64];
    float s = v0 + v1 + v2;
    #pragma unroll
    for (int o = 16; o > 0; o >>= 1) s += __shfl_xor_sync(0xffffffffu, s, o);
    float mu = s * (1.0f / 96.0f);
    float d0 = v0 - mu, d1 = v1 - mu, d2 = v2 - mu;
    float sq = d0 * d0 + d1 * d1 + d2 * d2;
    #pragma unroll
    for (int o = 16; o > 0; o >>= 1) sq += __shfl_xor_sync(0xffffffffu, sq, o);
    float inv = rsqrtf(sq * (1.0f / 96.0f) + 1e-5f);
    float* dst = out + (size_t)tok * 96;
    dst[lane]      = d0 * inv * g[lane]      + bt[lane];
    dst[lane + 32] = d1 * inv * g[lane + 32] + bt[lane + 32];
    dst[lane + 64] = d2 * inv * g[lane + 64] + bt[lane + 64];
}

// ---------------------------------------------------------------------------
// Tensor-core GEMM: out[m, n0+j] = act(A[m,:K] . wT[:, n0+j] + bias), modes.
// Block: 128 rows x 96 cols, 8 warps (4 Mquad x 2 Nhalf).
// Warp: 2 m-frags(16) x 6 n-frags(8). tf32 m16n8k8.
// Dynamic smem: As[128][AP] (AP%32==4), Ws[K][104].
// MODE 0 plain (outN cols), 1 proj: roll(+4,+4)+residual, 2 residual.
// ACT 0 none, 1 gelu.
// ---------------------------------------------------------------------------
template<int K, int ACT, int MODE>
__global__ void __launch_bounds__(256) gemm_mma(
        const float* __restrict__ A, const float* __restrict__ wT,
        const float* __restrict__ bias, const float* __restrict__ res,
        float* __restrict__ out, int Nld, int n0_off, int outN)
{
    constexpr int AP = (K == 96) ? 100 : 196;   // % 32 == 4
    extern __shared__ unsigned smem_u[];
    unsigned* As = smem_u;                 // 128*AP
    unsigned* Ws = smem_u + 128 * AP;      // K*104
    int m0 = blockIdx.x * 128;
    int n0 = (blockIdx.y + n0_off) * 96;
    int t  = threadIdx.x;
    int warp = t >> 5, lane = t & 31;
    int wm = warp >> 1, wn = warp & 1;
    int g = lane >> 2, tg = lane & 3;

    // stage A (tf32) -- coalesced reads, conflict-light stores
    #pragma unroll
    for (int i = 0; i < 128 * K / 256; i++) {
        int idx = t + i * 256;
        int m = idx / K, k = idx % K;
        As[m * AP + k] = f2tf(A[(size_t)(m0 + m) * K + k]);
    }
    // stage W
    #pragma unroll
    for (int i = 0; i < K * 96 / 256; i++) {
        int idx = t + i * 256;
        int k = idx / 96, c = idx % 96;
        Ws[k * 104 + c] = f2tf(wT[(size_t)k * Nld + n0 + c]);
    }
    __syncthreads();

    float acc[2][6][4];
    #pragma unroll
    for (int i = 0; i < 2; i++)
        #pragma unroll
        for (int j = 0; j < 6; j++)
            #pragma unroll
            for (int q = 0; q < 4; q++) acc[i][j][q] = 0.0f;

    #pragma unroll
    for (int s = 0; s < K / 8; s++) {
        int kb = s * 8;
        unsigned a[2][4];
        #pragma unroll
        for (int i = 0; i < 2; i++) {
            int mb = (wm * 2 + i) * 16;
            a[i][0] = As[(mb + g)     * AP + kb + tg];
            a[i][1] = As[(mb + g + 8) * AP + kb + tg];
            a[i][2] = As[(mb + g)     * AP + kb + tg + 4];
            a[i][3] = As[(mb + g + 8) * AP + kb + tg + 4];
        }
        unsigned b[6][2];
        #pragma unroll
        for (int j = 0; j < 6; j++) {
            int col = wn * 48 + j * 8 + g;
            b[j][0] = Ws[(kb + tg)     * 104 + col];
            b[j][1] = Ws[(kb + tg + 4) * 104 + col];
        }
        #pragma unroll
        for (int i = 0; i < 2; i++)
            #pragma unroll
            for (int j = 0; j < 6; j++) mma_tf32(acc[i][j], a[i], b[j]);
    }

    // epilogue
    #pragma unroll
    for (int i = 0; i < 2; i++) {
        int rb = m0 + (wm * 2 + i) * 16;
        #pragma unroll
        for (int j = 0; j < 6; j++) {
            int c = n0 + wn * 48 + j * 8 + tg * 2;
            #pragma unroll
            for (int half = 0; half < 2; half++) {
                int row = rb + g + half * 8;
                float v0 = acc[i][j][half * 2]     + bias[c];
                float v1 = acc[i][j][half * 2 + 1] + bias[c + 1];
                if (ACT == 1) { v0 = gelu_f(v0); v1 = gelu_f(v1); }
                if (MODE == 0) {
                    out[(size_t)row * outN + c]     = v0;
                    out[(size_t)row * outN + c + 1] = v1;
                } else if (MODE == 1) {
                    int bb = row >> 16, rr = row & 65535, hy = rr >> 8, wx = rr & 255;
                    int tr = (bb << 16) | (((hy + 4) & 255) << 8) | ((wx + 4) & 255);
                    out[(size_t)tr * 96 + c]     = res[(size_t)tr * 96 + c]     + v0;
                    out[(size_t)tr * 96 + c + 1] = res[(size_t)tr * 96 + c + 1] + v1;
                } else {
                    out[(size_t)row * 96 + c]     = res[(size_t)row * 96 + c]     + v0;
                    out[(size_t)row * 96 + c + 1] = res[(size_t)row * 96 + c + 1] + v1;
                }
            }
        }
    }
}

// ---------------------------------------------------------------------------
// Tensor-core 3x3 SAME conv (implicit GEMM), NHWC.
// Block: 16x16 pixel tile x 96 outputs; halo 18x18 in smem; K = 9*CIN by
// chunks of KC=16 channels. Warp: 4 m-frags(16 px) x 6 n-frags(8 co).
// grid.z = b*(COUT/96) + cohalf.
// ACT: 0 none, 1 relu, 2 gelu. RES: residual add.
// ---------------------------------------------------------------------------
template<int CIN, int COUT, int ACT, int RES>
__global__ void __launch_bounds__(256) conv_mma(
        const float* __restrict__ in, const float* __restrict__ w,
        const float* __restrict__ bias, const float* __restrict__ res,
        float* __restrict__ out)
{
    constexpr int KC = 16;
    constexpr int WP = 104;          // ws ci-pitch  (%32 == 8)
    constexpr int IP = 328;          // ins ci-pitch (%32 == 8)
    constexpr int NH = COUT / 96;
    extern __shared__ unsigned smem_u[];
    unsigned* ws_u  = smem_u;                   // [9][KC][WP]
    unsigned* ins_u = smem_u + 9 * KC * WP;     // [KC][IP] (324 used)

    int x0 = blockIdx.x * 16, y0 = blockIdx.y * 16;
    int zb = blockIdx.z;
    int cohalf = (NH == 1) ? 0 : (zb & 1);
    int b      = (NH == 1) ? zb : (zb >> 1);
    int t  = threadIdx.x;
    int warp = t >> 5, lane = t & 31;
    int wm = warp >> 1, wn = warp & 1;
    int g = lane >> 2, tg = lane & 3;

    float acc[4][6][4];
    #pragma unroll
    for (int i = 0; i < 4; i++)
        #pragma unroll
        for (int j = 0; j < 6; j++)
            #pragma unroll
            for (int q = 0; q < 4; q++) acc[i][j][q] = 0.0f;

    for (int ci0 = 0; ci0 < CIN; ci0 += KC) {
        // stage halo 18x18 x KC
        for (int idx = t; idx < 324 * KC; idx += 256) {
            int ci = idx & (KC - 1), pos = idx >> 4;
            int hp = pos / 18, wp = pos % 18;
            int gy = y0 + hp - 1, gx = x0 + wp - 1;
            float v = 0.0f;
            if ((unsigned)gy < 256u && (unsigned)gx < 256u)
                v = in[(size_t)((b << 16) | (gy << 8) | gx) * CIN + ci0 + ci];
            ins_u[ci * IP + pos] = f2tf(v);
        }
        // stage weights 9 x KC x 96 (this cohalf)
        for (int idx = t; idx < 9 * KC * 96; idx += 256) {
            int c = idx % 96;
            int r2 = idx / 96;
            int ci = r2 % KC, tap = r2 / KC;
            ws_u[(tap * KC + ci) * WP + c] =
                f2tf(w[((size_t)(tap * CIN + ci0 + ci)) * COUT + cohalf * 96 + c]);
        }
        __syncthreads();

        #pragma unroll
        for (int dy = 0; dy < 3; dy++) {
            #pragma unroll
            for (int dx = 0; dx < 3; dx++) {
                const unsigned* wt = ws_u + (dy * 3 + dx) * KC * WP;
                #pragma unroll
                for (int s = 0; s < KC / 8; s++) {
                    int cb = s * 8;
                    unsigned a[4][4];
                    #pragma unroll
                    for (int i = 0; i < 4; i++) {
                        int py = wm * 4 + i;                       // tile row
                        int base = (py + dy) * 18 + dx;
                        a[i][0] = ins_u[(cb + tg)     * IP + base + g];
                        a[i][1] = ins_u[(cb + tg)     * IP + base + g + 8];
                        a[i][2] = ins_u[(cb + tg + 4) * IP + base + g];
                        a[i][3] = ins_u[(cb + tg + 4) * IP + base + g + 8];
                    }
                    unsigned bfr[6][2];
                    #pragma unroll
                    for (int j = 0; j < 6; j++) {
                        int col = wn * 48 + j * 8 + g;
                        bfr[j][0] = wt[(cb + tg)     * WP + col];
                        bfr[j][1] = wt[(cb + tg + 4) * WP + col];
                    }
                    #pragma unroll
                    for (int i = 0; i < 4; i++)
                        #pragma unroll
                        for (int j = 0; j < 6; j++) mma_tf32(acc[i][j], a[i], bfr[j]);
                }
            }
        }
        __syncthreads();
    }

    // epilogue: pixel (y0 + wm*4+i, x0 + g (+8)), channel cohalf*96 + wn*48 + j*8 + tg*2
    #pragma unroll
    for (int i = 0; i < 4; i++) {
        int y = y0 + wm * 4 + i;
        #pragma unroll
        for (int j = 0; j < 6; j++) {
            int co = cohalf * 96 + wn * 48 + j * 8 + tg * 2;
            float b0 = bias[co], b1 = bias[co + 1];
            #pragma unroll
            for (int half = 0; half < 2; half++) {
                int x = x0 + g + half * 8;
                size_t base = (size_t)((b << 16) | (y << 8) | x) * COUT + co;
                float v0 = acc[i][j][half * 2]     + b0;
                float v1 = acc[i][j][half * 2 + 1] + b1;
                if (ACT == 1) { v0 = fmaxf(v0, 0.0f); v1 = fmaxf(v1, 0.0f); }
                if (ACT == 2) { v0 = gelu_f(v0); v1 = gelu_f(v1); }
                if (RES) { v0 += res[base]; v1 += res[base + 1]; }
                out[base]     = v0;
                out[base + 1] = v1;
            }
        }
    }
}

// ---------------------------------------------------------------------------
// Windowed dual attention. One block per (window, head). 64 threads = rows.
// ---------------------------------------------------------------------------
DEV int regio(int wblk, int i) { return (wblk < 31) ? 0 : ((i < 4) ? 1 : 2); }

DEV void attn_pass(const float4 (*K4)[4], const float4 (*V4)[4], const float4 q[4],
                   float lsv, const float* rpb_s, int i1, int j1, int cnt1,
                   int wh, int ww, float4 o[4])
{
    float s[64];
    #pragma unroll
    for (int m = 0; m < 64; m++) {
        const float4* kr = K4[m];
        float d;
        d  = q[0].x * kr[0].x + q[0].y * kr[0].y + q[0].z * kr[0].z + q[0].w * kr[0].w;
        d += q[1].x * kr[1].x + q[1].y * kr[1].y + q[1].z * kr[1].z + q[1].w * kr[1].w;
        d += q[2].x * kr[2].x + q[2].y * kr[2].y + q[2].z * kr[2].z + q[2].w * kr[2].w;
        d += q[3].x * kr[3].x + q[3].y * kr[3].y + q[3].z * kr[3].z + q[3].w * kr[3].w;
        int i2 = m >> 3, j2 = m & 7;
        float rb = rpb_s[(i1 - i2 + 7) * 15 + (j1 - j2 + 7)];
        int cnt2 = regio(wh, i2) * 3 + regio(ww, j2);
        s[m] = d * lsv + rb + ((cnt1 != cnt2) ? -100.0f : 0.0f);
    }
    float mx = s[0];
    #pragma unroll
    for (int m = 1; m < 64; m++) mx = fmaxf(mx, s[m]);
    float sum = 0.0f;
    float4 a0 = make_float4(0, 0, 0, 0), a1 = a0, a2 = a0, a3 = a0;
    #pragma unroll
    for (int m = 0; m < 64; m++) {
        float p = expf(s[m] - mx);
        sum += p;
        const float4* vr = V4[m];
        a0.x += p * vr[0].x; a0.y += p * vr[0].y; a0.z += p * vr[0].z; a0.w += p * vr[0].w;
        a1.x += p * vr[1].x; a1.y += p * vr[1].y; a1.z += p * vr[1].z; a1.w += p * vr[1].w;
        a2.x += p * vr[2].x; a2.y += p * vr[2].y; a2.z += p * vr[2].z; a2.w += p * vr[2].w;
        a3.x += p * vr[3].x; a3.y += p * vr[3].y; a3.z += p * vr[3].z; a3.w += p * vr[3].w;
    }
    float inv = 1.0f / sum;
    o[0] = make_float4(a0.x * inv, a0.y * inv, a0.z * inv, a0.w * inv);
    o[1] = make_float4(a1.x * inv, a1.y * inv, a1.z * inv, a1.w * inv);
    o[2] = make_float4(a2.x * inv, a2.y * inv, a2.z * inv, a2.w * inv);
    o[3] = make_float4(a3.x * inv, a3.y * inv, a3.z * inv, a3.w * inv);
}

__global__ void attn_kernel(const float* __restrict__ qkvx, const float* __restrict__ qkvr,
                            const float* __restrict__ lsp, const float* __restrict__ gat,
                            const float* __restrict__ rpbt, float* __restrict__ out)
{
    __shared__ float4 ks[64][4], vs[64][4], krs[64][4], vrs[64][4];
    __shared__ float rpb_s[225];
    int blk  = blockIdx.x;
    int head = blk % HEADS;
    int widx = blk / HEADS;
    int b  = widx >> 10;
    int nw = widx & 1023;
    int wh = nw >> 5, ww = nw & 31;
    int n  = threadIdx.x;
    int i1 = n >> 3, j1 = n & 7;

    size_t tok = (size_t)((b << 16) | ((wh * 8 + i1) << 8) | (ww * 8 + j1));
    size_t rowbase = tok * 288 + head * 16;

    float4 q[4];
    {
        const float4* qp = (const float4*)(qkvx + rowbase);
        q[0] = qp[0]; q[1] = qp[1]; q[2] = qp[2]; q[3] = qp[3];
        float ss = 0.0f;
        #pragma unroll
        for (int i = 0; i < 4; i++)
            ss += q[i].x * q[i].x + q[i].y * q[i].y + q[i].z * q[i].z + q[i].w * q[i].w;
        float inv = 1.0f / fmaxf(sqrtf(ss), 1e-12f);
        #pragma unroll
        for (int i = 0; i < 4; i++) { q[i].x *= inv; q[i].y *= inv; q[i].z *= inv; q[i].w *= inv; }
    }
    {
        const float4* kp = (const float4*)(qkvx + rowbase + 96);
        float4 kv[4] = {kp[0], kp[1], kp[2], kp[3]};
        float ss = 0.0f;
        #pragma unroll
        for (int i = 0; i < 4; i++)
            ss += kv[i].x * kv[i].x + kv[i].y * kv[i].y + kv[i].z * kv[i].z + kv[i].w * kv[i].w;
        float inv = 1.0f / fmaxf(sqrtf(ss), 1e-12f);
        #pragma unroll
        for (int i = 0; i < 4; i++)
            ks[n][i] = make_float4(kv[i].x * inv, kv[i].y * inv, kv[i].z * inv, kv[i].w * inv);
        const float4* vp = (const float4*)(qkvx + rowbase + 192);
        #pragma unroll
        for (int i = 0; i < 4; i++) vs[n][i] = vp[i];
    }
    {
        const float4* kp = (const float4*)(qkvr + rowbase + 96);
        float4 kv[4] = {kp[0], kp[1], kp[2], kp[3]};
        float ss = 0.0f;
        #pragma unroll
        for (int i = 0; i < 4; i++)
            ss += kv[i].x * kv[i].x + kv[i].y * kv[i].y + kv[i].z * kv[i].z + kv[i].w * kv[i].w;
        float inv = 1.0f / fmaxf(sqrtf(ss), 1e-12f);
        #pragma unroll
        for (int i = 0; i < 4; i++)
            krs[n][i] = make_float4(kv[i].x * inv, kv[i].y * inv, kv[i].z * inv, kv[i].w * inv);
        const float4* vp = (const float4*)(qkvr + rowbase + 192);
        #pragma unroll
        for (int i = 0; i < 4; i++) vrs[n][i] = vp[i];
    }
    for (int idx = n; idx < 225; idx += 64) rpb_s[idx] = rpbt[idx * 6 + head];

    float lsv = expf(fminf(lsp[head], 4.605170185988092f));
    float gv  = 1.0f / (1.0f + expf(-gat[head]));
    int cnt1 = regio(wh, i1) * 3 + regio(ww, j1);
    __syncthreads();

    float4 o1[4], o2[4];
    attn_pass(ks,  vs,  q, lsv, rpb_s, i1, j1, cnt1, wh, ww, o1);
    attn_pass(krs, vrs, q, lsv, rpb_s, i1, j1, cnt1, wh, ww, o2);

    float4* op = (float4*)(out + tok * 96 + head * 16);
    float og = 1.0f - gv;
    #pragma unroll
    for (int i = 0; i < 4; i++)
        op[i] = make_float4(og * o1[i].x + gv * o2[i].x,
                            og * o1[i].y + gv * o2[i].y,
                            og * o1[i].z + gv * o2[i].z,
                            og * o1[i].w + gv * o2[i].w);
}

// ---------------------------------------------------------------------------
// Host orchestration
// ---------------------------------------------------------------------------
static int g_attr_done = 0;

extern "C" void kernel_launch(void* const* d_in, const int* in_sizes, int n_in,
                              void* d_out, int out_size)
{
    const float* x       = (const float*)d_in[0];
    const float* ref     = (const float*)d_in[1];
    const float* n1g     = (const float*)d_in[2];
    const float* n1b     = (const float*)d_in[3];
    const float* qkv_w   = (const float*)d_in[4];
    const float* qkv_b   = (const float*)d_in[5];
    const float* lscale  = (const float*)d_in[6];
    const float* gating  = (const float*)d_in[7];
    const float* rpbt    = (const float*)d_in[8];
    const float* trunk_w = (const float*)d_in[9];
    const float* trunk_b = (const float*)d_in[10];
    const float* proj_w  = (const float*)d_in[11];
    const float* proj_b  = (const float*)d_in[12];
    const float* n2g     = (const float*)d_in[13];
    const float* n2b     = (const float*)d_in[14];
    const float* fc1_w   = (const float*)d_in[15];
    const float* fc1_b   = (const float*)d_in[16];
    const float* convm_w = (const float*)d_in[17];
    const float* convm_b = (const float*)d_in[18];
    const float* fc2_w   = (const float*)d_in[19];
    const float* fc2_b   = (const float*)d_in[20];
    float* out = (float*)d_out;

    float *lnx, *lnr, *qkvx, *qkvr, *ybuf, *tmp, *x2, *h1, *h2;
    float *qkvT, *projT, *fc1T, *fc2T;
    cudaGetSymbolAddress((void**)&lnx,  g_lnx);
    cudaGetSymbolAddress((void**)&lnr,  g_lnr);
    cudaGetSymbolAddress((void**)&qkvx, g_qkvx);
    cudaGetSymbolAddress((void**)&qkvr, g_qkvr);
    cudaGetSymbolAddress((void**)&ybuf, g_y);
    cudaGetSymbolAddress((void**)&tmp,  g_tmp);
    cudaGetSymbolAddress((void**)&x2,   g_x2);
    cudaGetSymbolAddress((void**)&h1,   g_h1);
    cudaGetSymbolAddress((void**)&h2,   g_h2);
    cudaGetSymbolAddress((void**)&qkvT, g_qkv_wT);
    cudaGetSymbolAddress((void**)&projT,g_proj_wT);
    cudaGetSymbolAddress((void**)&fc1T, g_fc1_wT);
    cudaGetSymbolAddress((void**)&fc2T, g_fc2_wT);

    const int CONV_SMEM  = (9 * 16 * 104 + 16 * 328) * 4;           // 80896
    const int GEMM_SMEM96  = (128 * 100 + 96 * 104) * 4;            // 91136
    const int GEMM_SMEM192 = (128 * 196 + 192 * 104) * 4;           // 180224

    if (!g_attr_done) {
        cudaFuncSetAttribute(conv_mma<96, 96, 1, 0>,  cudaFuncAttributeMaxDynamicSharedMemorySize, CONV_SMEM);
        cudaFuncSetAttribute(conv_mma<96, 96, 0, 1>,  cudaFuncAttributeMaxDynamicSharedMemorySize, CONV_SMEM);
        cudaFuncSetAttribute(conv_mma<192, 192, 2, 0>, cudaFuncAttributeMaxDynamicSharedMemorySize, CONV_SMEM);
        cudaFuncSetAttribute(gemm_mma<96, 0, 0>,  cudaFuncAttributeMaxDynamicSharedMemorySize, GEMM_SMEM96);
        cudaFuncSetAttribute(gemm_mma<96, 1, 0>,  cudaFuncAttributeMaxDynamicSharedMemorySize, GEMM_SMEM96);
        cudaFuncSetAttribute(gemm_mma<96, 0, 1>,  cudaFuncAttributeMaxDynamicSharedMemorySize, GEMM_SMEM96);
        cudaFuncSetAttribute(gemm_mma<192, 0, 2>, cudaFuncAttributeMaxDynamicSharedMemorySize, GEMM_SMEM192);
        g_attr_done = 1;
    }

    transpose_k<<<(288 * 96 + 255) / 256, 256>>>(qkv_w, qkvT, 288, 96);
    transpose_k<<<(96 * 96 + 255) / 256, 256>>>(proj_w, projT, 96, 96);
    transpose_k<<<(192 * 96 + 255) / 256, 256>>>(fc1_w, fc1T, 192, 96);
    transpose_k<<<(96 * 192 + 255) / 256, 256>>>(fc2_w, fc2T, 96, 192);

    ln_kernel<<<TOK / 8, 256>>>(x,   n1g, n1b, lnx, 4);
    ln_kernel<<<TOK / 8, 256>>>(ref, n1g, n1b, lnr, 4);

    gemm_mma<96, 0, 0><<<dim3(TOK / 128, 3), 256, GEMM_SMEM96>>>(lnx, qkvT, qkv_b, nullptr, qkvx, 288, 0, 288);
    gemm_mma<96, 0, 0><<<dim3(TOK / 128, 2), 256, GEMM_SMEM96>>>(lnr, qkvT, qkv_b, nullptr, qkvr, 288, 1, 288);

    attn_kernel<<<Bb * 1024 * HEADS, 64>>>(qkvx, qkvr, lscale, gating, rpbt, ybuf);

    conv_mma<96, 96, 1, 0><<<dim3(16, 16, Bb), 256, CONV_SMEM>>>(ybuf, trunk_w,             trunk_b,       nullptr, tmp);
    conv_mma<96, 96, 0, 1><<<dim3(16, 16, Bb), 256, CONV_SMEM>>>(tmp,  trunk_w + 1 * 82944, trunk_b + 96,  ybuf,    ybuf);
    conv_mma<96, 96, 1, 0><<<dim3(16, 16, Bb), 256, CONV_SMEM>>>(ybuf, trunk_w + 2 * 82944, trunk_b + 192, nullptr, tmp);
    conv_mma<96, 96, 0, 1><<<dim3(16, 16, Bb), 256, CONV_SMEM>>>(tmp,  trunk_w + 3 * 82944, trunk_b + 288, ybuf,    ybuf);

    gemm_mma<96, 0, 1><<<dim3(TOK / 128, 1), 256, GEMM_SMEM96>>>(ybuf, projT, proj_b, x, x2, 96, 0, 96);

    ln_kernel<<<TOK / 8, 256>>>(x2, n2g, n2b, tmp, 0);
    gemm_mma<96, 1, 0><<<dim3(TOK / 128, 2), 256, GEMM_SMEM96>>>(tmp, fc1T, fc1_b, nullptr, h1, 192, 0, 192);
    conv_mma<192, 192, 2, 0><<<dim3(16, 16, Bb * 2), 256, CONV_SMEM>>>(h1, convm_w, convm_b, nullptr, h2);
    gemm_mma<192, 0, 2><<<dim3(TOK / 128, 1), 256, GEMM_SMEM192>>>(h2, fc2T, fc2_b, x2, out, 96, 0, 96);
}

// round 5
// speedup vs baseline: 3.5275x; 1.6318x over previous
#include <cuda_runtime.h>
#include <cuda_fp16.h>
#include <math.h>

// ---------------------------------------------------------------------------
// Problem constants
// ---------------------------------------------------------------------------
constexpr int Bb   = 2;
constexpr int Cc   = 96;
constexpr int HEADS= 6;
constexpr int HID  = 192;
constexpr int TOK  = Bb * 256 * 256;          // 131072 tokens

// ---------------------------------------------------------------------------
// Static device scratch
// ---------------------------------------------------------------------------
__device__ float g_lnx [TOK * Cc];
__device__ float g_lnr [TOK * Cc];
__device__ float g_qkvx[TOK * 288];
__device__ float g_qkvr[TOK * 288];
__device__ float g_y   [TOK * Cc];
__device__ float g_tmp [TOK * Cc];
__device__ float g_x2  [TOK * Cc];
__device__ float g_h1  [TOK * HID];
__device__ float g_h2  [TOK * HID];

#define DEV __device__ __forceinline__

DEV float gelu_f(float v) { return 0.5f * v * (1.0f + erff(v * 0.70710678118654752f)); }

DEV unsigned packh2(float lo, float hi) {
    __half2 h = __floats2half2_rn(lo, hi);          // lo -> .x (low 16 bits)
    return *reinterpret_cast<unsigned*>(&h);
}

// D += A(16x16, f16, row) * B(16x8, f16, col), fp32 accum
DEV void mma_f16(float* c, const unsigned* a, const unsigned* b) {
    asm("mma.sync.aligned.m16n8k16.row.col.f32.f16.f16.f32 "
        "{%0,%1,%2,%3}, {%4,%5,%6,%7}, {%8,%9}, {%0,%1,%2,%3};"
        : "+f"(c[0]), "+f"(c[1]), "+f"(c[2]), "+f"(c[3])
        : "r"(a[0]), "r"(a[1]), "r"(a[2]), "r"(a[3]), "r"(b[0]), "r"(b[1]));
}

// ---------------------------------------------------------------------------
// LayerNorm over C=96, with optional (+shift,+shift) gather (implements roll)
// ---------------------------------------------------------------------------
__global__ void ln_kernel(const float* __restrict__ in, const float* __restrict__ g,
                          const float* __restrict__ bt, float* __restrict__ out, int shift)
{
    int gid  = blockIdx.x * blockDim.x + threadIdx.x;
    int tok  = gid >> 5;
    int lane = gid & 31;
    if (tok >= TOK) return;
    int b = tok >> 16, rr = tok & 65535, h = rr >> 8, w = rr & 255;
    const float* src = in + (size_t)((b << 16) | (((h + shift) & 255) << 8) | ((w + shift) & 255)) * 96;
    float v0 = src[lane], v1 = src[lane + 32], v2 = src[lane + 64];
    float s = v0 + v1 + v2;
    #pragma unroll
    for (int o = 16; o > 0; o >>= 1) s += __shfl_xor_sync(0xffffffffu, s, o);
    float mu = s * (1.0f / 96.0f);
    float d0 = v0 - mu, d1 = v1 - mu, d2 = v2 - mu;
    float sq = d0 * d0 + d1 * d1 + d2 * d2;
    #pragma unroll
    for (int o = 16; o > 0; o >>= 1) sq += __shfl_xor_sync(0xffffffffu, sq, o);
    float inv = rsqrtf(sq * (1.0f / 96.0f) + 1e-5f);
    float* dst = out + (size_t)tok * 96;
    dst[lane]      = d0 * inv * g[lane]      + bt[lane];
    dst[lane + 32] = d1 * inv * g[lane + 32] + bt[lane + 32];
    dst[lane + 64] = d2 * inv * g[lane + 64] + bt[lane + 64];
}

// ---------------------------------------------------------------------------
// Tensor-core GEMM (fp16 m16n8k16): out[m, n0+j] = act(A . W[n0+j,:] + bias).
// W is the ORIGINAL [out][K] weight (k-contiguous => col-major B frags).
// Block: 128 rows x 96 cols, 8 warps (4 Mquad x 2 Nhalf); warp 2x6 frags.
// Smem (u32 k-pairs): As[128][AP], Ws[96][AP], AP = K/2+4.
// MODE 0 plain (outN cols), 1 proj: roll(+4,+4)+residual, 2 residual.
// ACT 0 none, 1 gelu.
// ---------------------------------------------------------------------------
template<int K, int ACT, int MODE>
__global__ void __launch_bounds__(256) gemm_h(
        const float* __restrict__ A, const float* __restrict__ W,
        const float* __restrict__ bias, const float* __restrict__ res,
        float* __restrict__ out, int n0_off, int outN)
{
    constexpr int KP = K / 2;
    constexpr int AP = KP + 4;                  // 52 (%32=20) or 100 (%32=4)
    extern __shared__ unsigned smem_u[];
    unsigned* As = smem_u;                      // 128*AP
    unsigned* Ws = smem_u + 128 * AP;           // 96*AP
    int m0 = blockIdx.x * 128;
    int n0 = (blockIdx.y + n0_off) * 96;
    int t  = threadIdx.x;
    int warp = t >> 5, lane = t & 31;
    int wm = warp >> 1, wn = warp & 1;
    int g = lane >> 2, tg = lane & 3;

    #pragma unroll
    for (int i = 0; i < 128 * KP / 256; i++) {
        int idx = t + i * 256;
        int m = idx / KP, kp = idx % KP;
        float2 v = *reinterpret_cast<const float2*>(A + (size_t)(m0 + m) * K + 2 * kp);
        As[m * AP + kp] = packh2(v.x, v.y);
    }
    #pragma unroll
    for (int i = 0; i < 96 * KP / 256; i++) {
        int idx = t + i * 256;
        int c = idx / KP, kp = idx % KP;
        float2 v = *reinterpret_cast<const float2*>(W + (size_t)(n0 + c) * K + 2 * kp);
        Ws[c * AP + kp] = packh2(v.x, v.y);
    }
    __syncthreads();

    float acc[2][6][4];
    #pragma unroll
    for (int i = 0; i < 2; i++)
        #pragma unroll
        for (int j = 0; j < 6; j++)
            #pragma unroll
            for (int q = 0; q < 4; q++) acc[i][j][q] = 0.0f;

    #pragma unroll
    for (int s = 0; s < K / 16; s++) {
        int kb = s * 8;
        unsigned a[2][4];
        #pragma unroll
        for (int i = 0; i < 2; i++) {
            int mb = (wm * 2 + i) * 16;
            a[i][0] = As[(mb + g)     * AP + kb + tg];
            a[i][1] = As[(mb + g + 8) * AP + kb + tg];
            a[i][2] = As[(mb + g)     * AP + kb + tg + 4];
            a[i][3] = As[(mb + g + 8) * AP + kb + tg + 4];
        }
        unsigned b[6][2];
        #pragma unroll
        for (int j = 0; j < 6; j++) {
            int col = wn * 48 + j * 8 + g;
            b[j][0] = Ws[col * AP + kb + tg];
            b[j][1] = Ws[col * AP + kb + tg + 4];
        }
        #pragma unroll
        for (int i = 0; i < 2; i++)
            #pragma unroll
            for (int j = 0; j < 6; j++) mma_f16(acc[i][j], a[i], b[j]);
    }

    #pragma unroll
    for (int i = 0; i < 2; i++) {
        int rb = m0 + (wm * 2 + i) * 16;
        #pragma unroll
        for (int j = 0; j < 6; j++) {
            int c = n0 + wn * 48 + j * 8 + tg * 2;
            #pragma unroll
            for (int half = 0; half < 2; half++) {
                int row = rb + g + half * 8;
                float v0 = acc[i][j][half * 2]     + bias[c];
                float v1 = acc[i][j][half * 2 + 1] + bias[c + 1];
                if (ACT == 1) { v0 = gelu_f(v0); v1 = gelu_f(v1); }
                if (MODE == 0) {
                    out[(size_t)row * outN + c]     = v0;
                    out[(size_t)row * outN + c + 1] = v1;
                } else if (MODE == 1) {
                    int bb = row >> 16, rr = row & 65535, hy = rr >> 8, wx = rr & 255;
                    int tr = (bb << 16) | (((hy + 4) & 255) << 8) | ((wx + 4) & 255);
                    out[(size_t)tr * 96 + c]     = res[(size_t)tr * 96 + c]     + v0;
                    out[(size_t)tr * 96 + c + 1] = res[(size_t)tr * 96 + c + 1] + v1;
                } else {
                    out[(size_t)row * 96 + c]     = res[(size_t)row * 96 + c]     + v0;
                    out[(size_t)row * 96 + c + 1] = res[(size_t)row * 96 + c + 1] + v1;
                }
            }
        }
    }
}

// ---------------------------------------------------------------------------
// Tensor-core 3x3 SAME conv (implicit GEMM, fp16 m16n8k16), NHWC.
// Block: 16x16 pixel tile x 96 outputs; halo 18x18 in smem; channel chunk
// KC=32 (16 u32 k-pairs, 2 k-steps per tap). Warp: 4 m-frags x 6 n-frags.
// grid.z = b*(COUT/96) + cohalf. ACT: 0 none,1 relu,2 gelu. RES: residual.
// ---------------------------------------------------------------------------
template<int CIN, int COUT, int ACT, int RES>
__global__ void __launch_bounds__(256) conv_h(
        const float* __restrict__ in, const float* __restrict__ w,
        const float* __restrict__ bias, const float* __restrict__ res,
        float* __restrict__ out)
{
    constexpr int KC = 32;            // input channels per chunk
    constexpr int WPITCH = 20;        // k-pair pitch for weights (%32=20)
    constexpr int IP = 328;           // halo pos pitch (%32=8)
    constexpr int NH = COUT / 96;
    extern __shared__ unsigned smem_u[];
    unsigned* ws_u  = smem_u;                       // [9][96][WPITCH]
    unsigned* ins_u = smem_u + 9 * 96 * WPITCH;     // [16 cip][IP] (324 used)

    int x0 = blockIdx.x * 16, y0 = blockIdx.y * 16;
    int zb = blockIdx.z;
    int cohalf = (NH == 1) ? 0 : (zb & 1);
    int b      = (NH == 1) ? zb : (zb >> 1);
    int t  = threadIdx.x;
    int warp = t >> 5, lane = t & 31;
    int wm = warp >> 1, wn = warp & 1;
    int g = lane >> 2, tg = lane & 3;

    float acc[4][6][4];
    #pragma unroll
    for (int i = 0; i < 4; i++)
        #pragma unroll
        for (int j = 0; j < 6; j++)
            #pragma unroll
            for (int q = 0; q < 4; q++) acc[i][j][q] = 0.0f;

    for (int ci0 = 0; ci0 < CIN; ci0 += KC) {
        // stage halo 18x18 x KC, packed as u32 ci-pairs, cip fastest (coalesced)
        for (int idx = t; idx < 324 * 16; idx += 256) {
            int cip = idx & 15, pos = idx >> 4;
            int hp = pos / 18, wp = pos % 18;
            int gy = y0 + hp - 1, gx = x0 + wp - 1;
            unsigned pv = 0;
            if ((unsigned)gy < 256u && (unsigned)gx < 256u) {
                float2 v = *reinterpret_cast<const float2*>(
                    in + (size_t)((b << 16) | (gy << 8) | gx) * CIN + ci0 + 2 * cip);
                pv = packh2(v.x, v.y);
            }
            ins_u[cip * IP + pos] = pv;
        }
        // stage weights 9 x KC x 96 (this cohalf); co fastest (coalesced)
        for (int idx = t; idx < 9 * 16 * 96; idx += 256) {
            int co = idx % 96;
            int r2 = idx / 96;
            int cip = r2 % 16, tap = r2 / 16;
            size_t base = ((size_t)(tap * CIN + ci0 + 2 * cip)) * COUT + cohalf * 96 + co;
            ws_u[(tap * 96 + co) * WPITCH + cip] = packh2(w[base], w[base + COUT]);
        }
        __syncthreads();

        #pragma unroll
        for (int dy = 0; dy < 3; dy++) {
            #pragma unroll
            for (int dx = 0; dx < 3; dx++) {
                const unsigned* wt = ws_u + (dy * 3 + dx) * 96 * WPITCH;
                #pragma unroll
                for (int s = 0; s < 2; s++) {           // 2 k-steps of 16 ci
                    int cb = s * 8;
                    unsigned a[4][4];
                    #pragma unroll
                    for (int i = 0; i < 4; i++) {
                        int py = wm * 4 + i;
                        int base = (py + dy) * 18 + dx;
                        a[i][0] = ins_u[(cb + tg)     * IP + base + g];
                        a[i][1] = ins_u[(cb + tg)     * IP + base + g + 8];
                        a[i][2] = ins_u[(cb + tg + 4) * IP + base + g];
                        a[i][3] = ins_u[(cb + tg + 4) * IP + base + g + 8];
                    }
                    unsigned bfr[6][2];
                    #pragma unroll
                    for (int j = 0; j < 6; j++) {
                        int col = wn * 48 + j * 8 + g;
                        bfr[j][0] = wt[col * WPITCH + cb + tg];
                        bfr[j][1] = wt[col * WPITCH + cb + tg + 4];
                    }
                    #pragma unroll
                    for (int i = 0; i < 4; i++)
                        #pragma unroll
                        for (int j = 0; j < 6; j++) mma_f16(acc[i][j], a[i], bfr[j]);
                }
            }
        }
        __syncthreads();
    }

    #pragma unroll
    for (int i = 0; i < 4; i++) {
        int y = y0 + wm * 4 + i;
        #pragma unroll
        for (int j = 0; j < 6; j++) {
            int co = cohalf * 96 + wn * 48 + j * 8 + tg * 2;
            float b0 = bias[co], b1 = bias[co + 1];
            #pragma unroll
            for (int half = 0; half < 2; half++) {
                int x = x0 + g + half * 8;
                size_t base = (size_t)((b << 16) | (y << 8) | x) * COUT + co;
                float v0 = acc[i][j][half * 2]     + b0;
                float v1 = acc[i][j][half * 2 + 1] + b1;
                if (ACT == 1) { v0 = fmaxf(v0, 0.0f); v1 = fmaxf(v1, 0.0f); }
                if (ACT == 2) { v0 = gelu_f(v0); v1 = gelu_f(v1); }
                if (RES) { v0 += res[base]; v1 += res[base + 1]; }
                out[base]     = v0;
                out[base + 1] = v1;
            }
        }
    }
}

// ---------------------------------------------------------------------------
// Windowed dual attention. One block per (window, head). 64 threads = rows.
// ---------------------------------------------------------------------------
DEV int regio(int wblk, int i) { return (wblk < 31) ? 0 : ((i < 4) ? 1 : 2); }

DEV void attn_pass(const float4 (*K4)[4], const float4 (*V4)[4], const float4 q[4],
                   float lsv, const float* rpb_s, int i1, int j1, int cnt1,
                   int wh, int ww, float4 o[4])
{
    float s[64];
    #pragma unroll
    for (int m = 0; m < 64; m++) {
        const float4* kr = K4[m];
        float d;
        d  = q[0].x * kr[0].x + q[0].y * kr[0].y + q[0].z * kr[0].z + q[0].w * kr[0].w;
        d += q[1].x * kr[1].x + q[1].y * kr[1].y + q[1].z * kr[1].z + q[1].w * kr[1].w;
        d += q[2].x * kr[2].x + q[2].y * kr[2].y + q[2].z * kr[2].z + q[2].w * kr[2].w;
        d += q[3].x * kr[3].x + q[3].y * kr[3].y + q[3].z * kr[3].z + q[3].w * kr[3].w;
        int i2 = m >> 3, j2 = m & 7;
        float rb = rpb_s[(i1 - i2 + 7) * 15 + (j1 - j2 + 7)];
        int cnt2 = regio(wh, i2) * 3 + regio(ww, j2);
        s[m] = d * lsv + rb + ((cnt1 != cnt2) ? -100.0f : 0.0f);
    }
    float mx = s[0];
    #pragma unroll
    for (int m = 1; m < 64; m++) mx = fmaxf(mx, s[m]);
    float sum = 0.0f;
    float4 a0 = make_float4(0, 0, 0, 0), a1 = a0, a2 = a0, a3 = a0;
    #pragma unroll
    for (int m = 0; m < 64; m++) {
        float p = expf(s[m] - mx);
        sum += p;
        const float4* vr = V4[m];
        a0.x += p * vr[0].x; a0.y += p * vr[0].y; a0.z += p * vr[0].z; a0.w += p * vr[0].w;
        a1.x += p * vr[1].x; a1.y += p * vr[1].y; a1.z += p * vr[1].z; a1.w += p * vr[1].w;
        a2.x += p * vr[2].x; a2.y += p * vr[2].y; a2.z += p * vr[2].z; a2.w += p * vr[2].w;
        a3.x += p * vr[3].x; a3.y += p * vr[3].y; a3.z += p * vr[3].z; a3.w += p * vr[3].w;
    }
    float inv = 1.0f / sum;
    o[0] = make_float4(a0.x * inv, a0.y * inv, a0.z * inv, a0.w * inv);
    o[1] = make_float4(a1.x * inv, a1.y * inv, a1.z * inv, a1.w * inv);
    o[2] = make_float4(a2.x * inv, a2.y * inv, a2.z * inv, a2.w * inv);
    o[3] = make_float4(a3.x * inv, a3.y * inv, a3.z * inv, a3.w * inv);
}

__global__ void attn_kernel(const float* __restrict__ qkvx, const float* __restrict__ qkvr,
                            const float* __restrict__ lsp, const float* __restrict__ gat,
                            const float* __restrict__ rpbt, float* __restrict__ out)
{
    __shared__ float4 ks[64][4], vs[64][4], krs[64][4], vrs[64][4];
    __shared__ float rpb_s[225];
    int blk  = blockIdx.x;
    int head = blk % HEADS;
    int widx = blk / HEADS;
    int b  = widx >> 10;
    int nw = widx & 1023;
    int wh = nw >> 5, ww = nw & 31;
    int n  = threadIdx.x;
    int i1 = n >> 3, j1 = n & 7;

    size_t tok = (size_t)((b << 16) | ((wh * 8 + i1) << 8) | (ww * 8 + j1));
    size_t rowbase = tok * 288 + head * 16;

    float4 q[4];
    {
        const float4* qp = (const float4*)(qkvx + rowbase);
        q[0] = qp[0]; q[1] = qp[1]; q[2] = qp[2]; q[3] = qp[3];
        float ss = 0.0f;
        #pragma unroll
        for (int i = 0; i < 4; i++)
            ss += q[i].x * q[i].x + q[i].y * q[i].y + q[i].z * q[i].z + q[i].w * q[i].w;
        float inv = 1.0f / fmaxf(sqrtf(ss), 1e-12f);
        #pragma unroll
        for (int i = 0; i < 4; i++) { q[i].x *= inv; q[i].y *= inv; q[i].z *= inv; q[i].w *= inv; }
    }
    {
        const float4* kp = (const float4*)(qkvx + rowbase + 96);
        float4 kv[4] = {kp[0], kp[1], kp[2], kp[3]};
        float ss = 0.0f;
        #pragma unroll
        for (int i = 0; i < 4; i++)
            ss += kv[i].x * kv[i].x + kv[i].y * kv[i].y + kv[i].z * kv[i].z + kv[i].w * kv[i].w;
        float inv = 1.0f / fmaxf(sqrtf(ss), 1e-12f);
        #pragma unroll
        for (int i = 0; i < 4; i++)
            ks[n][i] = make_float4(kv[i].x * inv, kv[i].y * inv, kv[i].z * inv, kv[i].w * inv);
        const float4* vp = (const float4*)(qkvx + rowbase + 192);
        #pragma unroll
        for (int i = 0; i < 4; i++) vs[n][i] = vp[i];
    }
    {
        const float4* kp = (const float4*)(qkvr + rowbase + 96);
        float4 kv[4] = {kp[0], kp[1], kp[2], kp[3]};
        float ss = 0.0f;
        #pragma unroll
        for (int i = 0; i < 4; i++)
            ss += kv[i].x * kv[i].x + kv[i].y * kv[i].y + kv[i].z * kv[i].z + kv[i].w * kv[i].w;
        float inv = 1.0f / fmaxf(sqrtf(ss), 1e-12f);
        #pragma unroll
        for (int i = 0; i < 4; i++)
            krs[n][i] = make_float4(kv[i].x * inv, kv[i].y * inv, kv[i].z * inv, kv[i].w * inv);
        const float4* vp = (const float4*)(qkvr + rowbase + 192);
        #pragma unroll
        for (int i = 0; i < 4; i++) vrs[n][i] = vp[i];
    }
    for (int idx = n; idx < 225; idx += 64) rpb_s[idx] = rpbt[idx * 6 + head];

    float lsv = expf(fminf(lsp[head], 4.605170185988092f));
    float gv  = 1.0f / (1.0f + expf(-gat[head]));
    int cnt1 = regio(wh, i1) * 3 + regio(ww, j1);
    __syncthreads();

    float4 o1[4], o2[4];
    attn_pass(ks,  vs,  q, lsv, rpb_s, i1, j1, cnt1, wh, ww, o1);
    attn_pass(krs, vrs, q, lsv, rpb_s, i1, j1, cnt1, wh, ww, o2);

    float4* op = (float4*)(out + tok * 96 + head * 16);
    float og = 1.0f - gv;
    #pragma unroll
    for (int i = 0; i < 4; i++)
        op[i] = make_float4(og * o1[i].x + gv * o2[i].x,
                            og * o1[i].y + gv * o2[i].y,
                            og * o1[i].z + gv * o2[i].z,
                            og * o1[i].w + gv * o2[i].w);
}

// ---------------------------------------------------------------------------
// Host orchestration
// ---------------------------------------------------------------------------
static int g_attr_done = 0;

extern "C" void kernel_launch(void* const* d_in, const int* in_sizes, int n_in,
                              void* d_out, int out_size)
{
    const float* x       = (const float*)d_in[0];
    const float* ref     = (const float*)d_in[1];
    const float* n1g     = (const float*)d_in[2];
    const float* n1b     = (const float*)d_in[3];
    const float* qkv_w   = (const float*)d_in[4];
    const float* qkv_b   = (const float*)d_in[5];
    const float* lscale  = (const float*)d_in[6];
    const float* gating  = (const float*)d_in[7];
    const float* rpbt    = (const float*)d_in[8];
    const float* trunk_w = (const float*)d_in[9];
    const float* trunk_b = (const float*)d_in[10];
    const float* proj_w  = (const float*)d_in[11];
    const float* proj_b  = (const float*)d_in[12];
    const float* n2g     = (const float*)d_in[13];
    const float* n2b     = (const float*)d_in[14];
    const float* fc1_w   = (const float*)d_in[15];
    const float* fc1_b   = (const float*)d_in[16];
    const float* convm_w = (const float*)d_in[17];
    const float* convm_b = (const float*)d_in[18];
    const float* fc2_w   = (const float*)d_in[19];
    const float* fc2_b   = (const float*)d_in[20];
    float* out = (float*)d_out;

    float *lnx, *lnr, *qkvx, *qkvr, *ybuf, *tmp, *x2, *h1, *h2;
    cudaGetSymbolAddress((void**)&lnx,  g_lnx);
    cudaGetSymbolAddress((void**)&lnr,  g_lnr);
    cudaGetSymbolAddress((void**)&qkvx, g_qkvx);
    cudaGetSymbolAddress((void**)&qkvr, g_qkvr);
    cudaGetSymbolAddress((void**)&ybuf, g_y);
    cudaGetSymbolAddress((void**)&tmp,  g_tmp);
    cudaGetSymbolAddress((void**)&x2,   g_x2);
    cudaGetSymbolAddress((void**)&h1,   g_h1);
    cudaGetSymbolAddress((void**)&h2,   g_h2);

    const int CONV_SMEM    = (9 * 96 * 20 + 16 * 328) * 4;   // 90112
    const int GEMM_SMEM96  = (128 * 52 + 96 * 52) * 4;       // 46592
    const int GEMM_SMEM192 = (128 * 100 + 96 * 100) * 4;     // 89600

    if (!g_attr_done) {
        cudaFuncSetAttribute(conv_h<96, 96, 1, 0>,   cudaFuncAttributeMaxDynamicSharedMemorySize, CONV_SMEM);
        cudaFuncSetAttribute(conv_h<96, 96, 0, 1>,   cudaFuncAttributeMaxDynamicSharedMemorySize, CONV_SMEM);
        cudaFuncSetAttribute(conv_h<192, 192, 2, 0>, cudaFuncAttributeMaxDynamicSharedMemorySize, CONV_SMEM);
        cudaFuncSetAttribute(gemm_h<96, 0, 0>,  cudaFuncAttributeMaxDynamicSharedMemorySize, GEMM_SMEM96);
        cudaFuncSetAttribute(gemm_h<96, 1, 0>,  cudaFuncAttributeMaxDynamicSharedMemorySize, GEMM_SMEM96);
        cudaFuncSetAttribute(gemm_h<96, 0, 1>,  cudaFuncAttributeMaxDynamicSharedMemorySize, GEMM_SMEM96);
        cudaFuncSetAttribute(gemm_h<192, 0, 2>, cudaFuncAttributeMaxDynamicSharedMemorySize, GEMM_SMEM192);
        g_attr_done = 1;
    }

    ln_kernel<<<TOK / 8, 256>>>(x,   n1g, n1b, lnx, 4);
    ln_kernel<<<TOK / 8, 256>>>(ref, n1g, n1b, lnr, 4);

    gemm_h<96, 0, 0><<<dim3(TOK / 128, 3), 256, GEMM_SMEM96>>>(lnx, qkv_w, qkv_b, nullptr, qkvx, 0, 288);
    gemm_h<96, 0, 0><<<dim3(TOK / 128, 2), 256, GEMM_SMEM96>>>(lnr, qkv_w, qkv_b, nullptr, qkvr, 1, 288);

    attn_kernel<<<Bb * 1024 * HEADS, 64>>>(qkvx, qkvr, lscale, gating, rpbt, ybuf);

    conv_h<96, 96, 1, 0><<<dim3(16, 16, Bb), 256, CONV_SMEM>>>(ybuf, trunk_w,             trunk_b,       nullptr, tmp);
    conv_h<96, 96, 0, 1><<<dim3(16, 16, Bb), 256, CONV_SMEM>>>(tmp,  trunk_w + 1 * 82944, trunk_b + 96,  ybuf,    ybuf);
    conv_h<96, 96, 1, 0><<<dim3(16, 16, Bb), 256, CONV_SMEM>>>(ybuf, trunk_w + 2 * 82944, trunk_b + 192, nullptr, tmp);
    conv_h<96, 96, 0, 1><<<dim3(16, 16, Bb), 256, CONV_SMEM>>>(tmp,  trunk_w + 3 * 82944, trunk_b + 288, ybuf,    ybuf);

    gemm_h<96, 0, 1><<<dim3(TOK / 128, 1), 256, GEMM_SMEM96>>>(ybuf, proj_w, proj_b, x, x2, 0, 96);

    ln_kernel<<<TOK / 8, 256>>>(x2, n2g, n2b, tmp, 0);
    gemm_h<96, 1, 0><<<dim3(TOK / 128, 2), 256, GEMM_SMEM96>>>(tmp, fc1_w, fc1_b, nullptr, h1, 0, 192);
    conv_h<192, 192, 2, 0><<<dim3(16, 16, Bb * 2), 256, CONV_SMEM>>>(h1, convm_w, convm_b, nullptr, h2);
    gemm_h<192, 0, 2><<<dim3(TOK / 128, 1), 256, GEMM_SMEM192>>>(h2, fc2_w, fc2_b, x2, out, 0, 96);
}